// round 9
// baseline (speedup 1.0000x reference)
#include <cuda_runtime.h>
#include <cuda_fp16.h>
#include <math.h>
#include <stdint.h>

// Problem shape: n=2, l=2048, d_model=1024, h=16, e=64
#define NB 2
#define SEQL 2048
#define DM 1024
#define NH 16
#define DE 64
#define ROWS (NB * SEQL)          // 4096

// ---------------- scratch ----------------
__device__ float  g_cwp[8 * NB * DM];         // cond partials
__device__ float  g_cw[NB * DM];
__device__ __half g_qkv[ROWS * 3 * DM];
__device__ __half g_xnh[ROWS * DM];
__device__ __half g_qh[NB*NH*SEQL*DE];
__device__ __half g_kh[NB*NH*SEQL*DE];
__device__ __half g_vh[NB*NH*SEQL*DE];
__device__ __half g_oh[ROWS * DM];
__device__ __half g_wqh[DM * 3 * DM], g_wql[DM * 3 * DM];
__device__ __half g_woh[DM * DM],     g_wol[DM * DM];

// ---------------- helpers ----------------
static __device__ __forceinline__ uint32_t smem_u32(const void* p) {
    uint32_t a;
    asm("{ .reg .u64 t; cvta.to.shared.u64 t, %1; cvt.u32.u64 %0, t; }" : "=r"(a) : "l"(p));
    return a;
}
static __device__ __forceinline__ void cpasync16(uint32_t dst, const void* src) {
    asm volatile("cp.async.cg.shared.global [%0], [%1], 16;" :: "r"(dst), "l"(src));
}
#define CP_COMMIT() asm volatile("cp.async.commit_group;" ::: "memory")
#define CP_WAIT1()  asm volatile("cp.async.wait_group 1;"  ::: "memory")
#define CP_WAIT0()  asm volatile("cp.async.wait_group 0;"  ::: "memory")
static __device__ __forceinline__ void ldsm4(uint32_t* r, uint32_t a) {
    asm volatile("ldmatrix.sync.aligned.m8n8.x4.shared.b16 {%0,%1,%2,%3}, [%4];"
        : "=r"(r[0]), "=r"(r[1]), "=r"(r[2]), "=r"(r[3]) : "r"(a));
}
static __device__ __forceinline__ void ldsm4t(uint32_t* r, uint32_t a) {
    asm volatile("ldmatrix.sync.aligned.m8n8.x4.trans.shared.b16 {%0,%1,%2,%3}, [%4];"
        : "=r"(r[0]), "=r"(r[1]), "=r"(r[2]), "=r"(r[3]) : "r"(a));
}
static __device__ __forceinline__ void mma_f16(float* c, const uint32_t* a, const uint32_t* b) {
    asm volatile("mma.sync.aligned.m16n8k16.row.col.f32.f16.f16.f32 "
        "{%0,%1,%2,%3}, {%4,%5,%6,%7}, {%8,%9}, {%0,%1,%2,%3};"
        : "+f"(c[0]), "+f"(c[1]), "+f"(c[2]), "+f"(c[3])
        : "r"(a[0]), "r"(a[1]), "r"(a[2]), "r"(a[3]), "r"(b[0]), "r"(b[1]));
}
static __device__ __forceinline__ float fast_exp2(float x) {
    float y; asm("ex2.approx.f32 %0, %1;" : "=f"(y) : "f"(x)); return y;
}
static __device__ __forceinline__ uint32_t packh(__half a, __half b) {
    return (uint32_t)__half_as_ushort(a) | ((uint32_t)__half_as_ushort(b) << 16);
}

// ---------------- cond GEMM: K-split partials + reduce ----------------
__global__ void cond_partial_kernel(const float* __restrict__ cond,
                                    const float* __restrict__ w_cond)
{
    __shared__ float cs[128];
    const int n  = blockIdx.y;
    const int ks = blockIdx.z;
    if (threadIdx.x < 128)
        cs[threadIdx.x] = cond[n * DM + ks * 128 + threadIdx.x];
    __syncthreads();
    const int j = blockIdx.x * blockDim.x + threadIdx.x;
    float acc = 0.f;
#pragma unroll 8
    for (int k = 0; k < 128; k++)
        acc = fmaf(cs[k], w_cond[(size_t)(ks * 128 + k) * DM + j], acc);
    g_cwp[(ks * NB + n) * DM + j] = acc;
}
__global__ void cond_reduce_kernel()
{
    const int i = blockIdx.x * blockDim.x + threadIdx.x;
    const int n = i / DM, j = i % DM;
    float s = 1.0f;
#pragma unroll
    for (int ks = 0; ks < 8; ks++)
        s += g_cwp[(ks * NB + n) * DM + j];
    g_cw[i] = s;
}

// ---------------- fused: rmsnorm(x) + split(w_qkv) + split(w_out) ----------------
#define FP_RMS   ROWS
#define FP_WQ    (DM * 3 * DM / 256)     // 12288
#define FP_WO    (DM * DM / 256)         // 4096
__global__ void fused_pre_kernel(const float* __restrict__ x,
                                 const float* __restrict__ w_qkv,
                                 const float* __restrict__ w_out)
{
    const int b = blockIdx.x;
    const int t = threadIdx.x;
    if (b < FP_RMS) {
        const int row = b;
        const int n = row / SEQL;
        float4 v = *(const float4*)(x + (size_t)row * DM + t * 4);
        float ss = v.x * v.x + v.y * v.y + v.z * v.z + v.w * v.w;
#pragma unroll
        for (int o = 16; o > 0; o >>= 1)
            ss += __shfl_xor_sync(0xffffffffu, ss, o);
        __shared__ float ws[8];
        if ((t & 31) == 0) ws[t >> 5] = ss;
        __syncthreads();
        float tot = ws[0]+ws[1]+ws[2]+ws[3]+ws[4]+ws[5]+ws[6]+ws[7];
        float rinv = rsqrtf(tot * (1.0f / DM) + 1e-6f);
        float4 cwv = *(const float4*)(g_cw + n * DM + t * 4);
        size_t base = (size_t)row * DM + t * 4;
        *(uint32_t*)(g_xnh + base)     = packh(__float2half_rn(v.x * cwv.x * rinv),
                                               __float2half_rn(v.y * cwv.y * rinv));
        *(uint32_t*)(g_xnh + base + 2) = packh(__float2half_rn(v.z * cwv.z * rinv),
                                               __float2half_rn(v.w * cwv.w * rinv));
    } else if (b < FP_RMS + FP_WQ) {
        int i = (b - FP_RMS) * 256 + t;
        float v = w_qkv[i];
        __half hh = __float2half_rn(v);
        g_wqh[i] = hh;
        g_wql[i] = __float2half_rn(v - __half2float(hh));
    } else {
        int i = (b - FP_RMS - FP_WQ) * 256 + t;
        float v = w_out[i];
        __half hh = __float2half_rn(v);
        g_woh[i] = hh;
        g_wol[i] = __float2half_rn(v - __half2float(hh));
    }
}

// ---------------- mma GEMM: C = Ah @ (Bh + Bl), 2-term, BK=64, 2-stage ----------------
// BM=128, BN=128, BK=64, 256 threads (8 warps, 4x2).
#define GM_ASTRIDE 144                        // 64 halves * 2B + 16 pad
#define GM_BSTRIDE 272
#define GM_A_SZ (128 * GM_ASTRIDE)            // 18432
#define GM_B_SZ (64 * GM_BSTRIDE)             // 17408
#define GM_BUF (GM_A_SZ + 2*GM_B_SZ)          // 53248
#define GEMM_SMEM (2 * GM_BUF)                // 106496  (2 CTAs/SM: 213KB <= 228KB)

static __device__ __forceinline__ void gemm_load(uint32_t smb, int bufi,
    const __half* Ah, const __half* Bh, const __half* Bl,
    int m0, int n0, int k0, int K, int N, int tid)
{
    uint32_t base = smb + bufi * GM_BUF;
    // A: 128 rows x 64 halves; 2 threads/row, 64B each
    const int ar = tid >> 1, ac = (tid & 1) * 32;
    const __half* pah = Ah + (size_t)(m0 + ar) * K + k0 + ac;
    uint32_t da = base + ar * GM_ASTRIDE + ac * 2;
#pragma unroll
    for (int c = 0; c < 4; c++)
        cpasync16(da + c * 16, pah + c * 8);
    // B: 64 rows x 128 halves, hi+lo; 4 threads/row, 64B each
    const int br = tid >> 2, bc = (tid & 3) * 32;
    const __half* pbh = Bh + (size_t)(k0 + br) * N + n0 + bc;
    const __half* pbl = Bl + (size_t)(k0 + br) * N + n0 + bc;
    uint32_t db = base + GM_A_SZ + br * GM_BSTRIDE + bc * 2;
#pragma unroll
    for (int c = 0; c < 4; c++) {
        cpasync16(db + c * 16,           pbh + c * 8);
        cpasync16(db + GM_B_SZ + c * 16, pbl + c * 8);
    }
}

template<int HOUT>
__global__ __launch_bounds__(256, 2) void mma_gemm_kernel(
    const __half* __restrict__ Ah,
    const __half* __restrict__ Bh, const __half* __restrict__ Bl,
    void* __restrict__ Cp, int M, int N, int K)
{
    extern __shared__ char sm[];
    const uint32_t smb = smem_u32(sm);
    const int tid = threadIdx.x, lane = tid & 31, wid = tid >> 5;
    const int m0 = blockIdx.y * 128, n0 = blockIdx.x * 128;
    const int wm = (wid & 3) * 32, wn = (wid >> 2) * 64;

    float acc[2][8][4];
#pragma unroll
    for (int m = 0; m < 2; m++)
#pragma unroll
        for (int n = 0; n < 8; n++)
#pragma unroll
            for (int r = 0; r < 4; r++) acc[m][n][r] = 0.f;

    const int nk = K / 64;                    // 16 steps
    gemm_load(smb, 0, Ah, Bh, Bl, m0, n0, 0, K, N, tid);
    CP_COMMIT();

    for (int s = 0; s < nk; s++) {
        CP_WAIT0();                 // stage s resident
        __syncthreads();
        if (s + 1 < nk)
            gemm_load(smb, (s + 1) & 1, Ah, Bh, Bl, m0, n0, (s + 1) * 64, K, N, tid);
        CP_COMMIT();

        uint32_t base = smb + (s & 1) * GM_BUF;
        uint32_t a_h = base;
        uint32_t b_h = base + GM_A_SZ, b_l = b_h + GM_B_SZ;
#pragma unroll
        for (int kt = 0; kt < 4; kt++) {
            uint32_t bfh[4][4], bfl[4][4];
            const uint32_t brow = kt * 16 + (lane & 7) + ((lane & 8) ? 8 : 0);
            const uint32_t bcol = wn * 2 + ((lane & 16) ? 16 : 0);
#pragma unroll
            for (int np = 0; np < 4; np++) {
                ldsm4t(bfh[np], b_h + brow * GM_BSTRIDE + bcol + np * 32);
                ldsm4t(bfl[np], b_l + brow * GM_BSTRIDE + bcol + np * 32);
            }
#pragma unroll
            for (int m = 0; m < 2; m++) {
                uint32_t afh[4];
                const uint32_t arow = wm + m * 16 + (lane & 15);
                const uint32_t acol = kt * 32 + ((lane & 16) ? 16 : 0);
                ldsm4(afh, a_h + arow * GM_ASTRIDE + acol);
                // hi terms first (8 independent accumulator targets), then lo
#pragma unroll
                for (int np = 0; np < 4; np++) {
                    mma_f16(acc[m][2*np],   afh, bfh[np]);
                    mma_f16(acc[m][2*np+1], afh, bfh[np] + 2);
                }
#pragma unroll
                for (int np = 0; np < 4; np++) {
                    mma_f16(acc[m][2*np],   afh, bfl[np]);
                    mma_f16(acc[m][2*np+1], afh, bfl[np] + 2);
                }
            }
        }
    }

    const int g = lane >> 2, tg = lane & 3;
#pragma unroll
    for (int m = 0; m < 2; m++)
#pragma unroll
        for (int rr = 0; rr < 2; rr++) {
            int row = m0 + wm + m * 16 + g + rr * 8;
#pragma unroll
            for (int n = 0; n < 8; n++) {
                int col = n0 + wn + n * 8 + tg * 2;
                if (HOUT) {
                    __half* C = (__half*)Cp;
                    *(uint32_t*)(C + (size_t)row * N + col) =
                        packh(__float2half_rn(acc[m][n][rr*2]),
                              __float2half_rn(acc[m][n][rr*2+1]));
                } else {
                    float* C = (float*)Cp;
                    *(float2*)(C + (size_t)row * N + col) =
                        make_float2(acc[m][n][rr*2], acc[m][n][rr*2+1]);
                }
            }
        }
}

// ---------------- qk rmsnorm + rope -> fp16 Q,K,V ----------------
__global__ void qknorm_rope_kernel(const float* __restrict__ pos,
                                   const float* __restrict__ qk_scale)
{
    const int row  = blockIdx.x;
    const int n    = row / SEQL;
    const int l    = row % SEQL;
    const int warp = threadIdx.x >> 5;
    const int lane = threadIdx.x & 31;
    const int head = blockIdx.y * 4 + warp;

    const __half* base = g_qkv + (size_t)row * (3 * DM);
    const int d1 = lane, d2 = lane + 32;

    float qa = __half2float(base[head * DE + d1]);
    float qb = __half2float(base[head * DE + d2]);
    float ka = __half2float(base[DM + head * DE + d1]);
    float kb = __half2float(base[DM + head * DE + d2]);
    __half va = base[2 * DM + head * DE + d1];
    __half vb = base[2 * DM + head * DE + d2];

    float ssq = qa * qa + qb * qb;
    float ssk = ka * ka + kb * kb;
#pragma unroll
    for (int o = 16; o > 0; o >>= 1) {
        ssq += __shfl_xor_sync(0xffffffffu, ssq, o);
        ssk += __shfl_xor_sync(0xffffffffu, ssk, o);
    }

    float sc = expf(0.5f * fminf(qk_scale[head], 4.6051701860f) - 1.0397207708f);
    float rq = sc * rsqrtf(ssq * (1.0f / DE) + 1e-6f);
    float rk = sc * rsqrtf(ssk * (1.0f / DE) + 1e-6f);
    qa *= rq; qb *= rq; ka *= rk; kb *= rk;

    float pv = pos[(size_t)row * 2 + (lane >> 4)];
    int   j  = lane & 15;
    float fr = expf(1.14472988584940017f + (float)(j * 16 + head) * (2.30258509299404568f / 256.0f));
    float th = pv * fr;
    float cth = cosf(th), sth = sinf(th);

    float qo1 = qa * cth - qb * sth, qo2 = qb * cth + qa * sth;
    float ko1 = ka * cth - kb * sth, ko2 = kb * cth + ka * sth;

    size_t ob = ((size_t)(n * NH + head) * SEQL + l) * DE;
    g_qh[ob + d1] = __float2half_rn(qo1);
    g_qh[ob + d2] = __float2half_rn(qo2);
    g_kh[ob + d1] = __float2half_rn(ko1);
    g_kh[ob + d2] = __float2half_rn(ko2);
    g_vh[ob + d1] = va;
    g_vh[ob + d2] = vb;
}

// ---------------- attention via mma.sync (fp16 QKV, fp32 accum), 3-stage ----------------
// CTA: 128 q-rows x (head,batch), 4 warps, TK=64 keys/tile, 32 tiles.
#define AT_STRIDE 144
#define AT_QH 0
#define AT_KV0 (128 * AT_STRIDE)              // 18432
#define AT_ARR (64 * AT_STRIDE)               // 9216 per array
#define AT_BUF (2 * AT_ARR)                   // 18432 (Kh, Vh)
#define NKT (SEQL / 64)                       // 32
#define ATTN_SMEM (AT_KV0 + 3 * AT_BUF)       // 73728

static __device__ __forceinline__ void attn_load_kv(uint32_t smb, size_t bh,
                                                    int tid, int t, int bufi)
{
    const int k0 = t * 64;
    const int r  = tid >> 1;
    const int hc = (tid & 1) * 32;
    uint32_t base = smb + AT_KV0 + bufi * AT_BUF + r * AT_STRIDE + hc * 2;
    const __half* s0 = g_kh + (bh + k0 + r) * DE + hc;
    const __half* s1 = g_vh + (bh + k0 + r) * DE + hc;
#pragma unroll
    for (int c = 0; c < 4; c++) {
        cpasync16(base + 0*AT_ARR + c*16, s0 + c*8);
        cpasync16(base + 1*AT_ARR + c*16, s1 + c*8);
    }
}

__global__ __launch_bounds__(128) void attn_mma_kernel()
{
    extern __shared__ char sm[];
    const uint32_t smb = smem_u32(sm);
    const int tid = threadIdx.x, lane = tid & 31, wid = tid >> 5;
    const int q0 = blockIdx.x * 128, head = blockIdx.y, b = blockIdx.z;
    const size_t bh = (size_t)(b * NH + head) * SEQL;
    const float SCL2 = 0.18033688011112042f;   // log2(e)/8

    {
        const __half* qh = g_qh + (bh + q0 + tid) * DE;
        uint32_t dh = smb + AT_QH + tid * AT_STRIDE;
#pragma unroll
        for (int c = 0; c < 8; c++)
            cpasync16(dh + c*16, qh + c*8);
    }
    attn_load_kv(smb, bh, tid, 0, 0);
    CP_COMMIT();
    attn_load_kv(smb, bh, tid, 1, 1);
    CP_COMMIT();
    CP_WAIT1();                 // Q + kv0 resident
    __syncthreads();

    uint32_t qfr[2][4][4];
#pragma unroll
    for (int m = 0; m < 2; m++)
#pragma unroll
        for (int kt = 0; kt < 4; kt++) {
            const uint32_t qrow = wid*32 + m*16 + (lane & 15);
            const uint32_t qcol = kt * 32 + ((lane & 16) ? 16 : 0);
            ldsm4(qfr[m][kt], smb + AT_QH + qrow * AT_STRIDE + qcol);
        }

    float O[2][8][4];
#pragma unroll
    for (int m = 0; m < 2; m++)
#pragma unroll
        for (int n = 0; n < 8; n++)
#pragma unroll
            for (int r = 0; r < 4; r++) O[m][n][r] = 0.f;
    float ls[2][2] = {{0.f, 0.f}, {0.f, 0.f}};

    for (int t = 0; t < NKT; t++) {
        CP_WAIT1();                 // kv(t) resident, kv(t+1) in flight
        __syncthreads();
        if (t + 2 < NKT)
            attn_load_kv(smb, bh, tid, t + 2, (t + 2) % 3);
        CP_COMMIT();

        uint32_t kb  = smb + AT_KV0 + (t % 3) * AT_BUF;
        uint32_t kh_b = kb, vh_b = kb + AT_ARR;

        float S[2][8][4];
#pragma unroll
        for (int m = 0; m < 2; m++)
#pragma unroll
            for (int n = 0; n < 8; n++)
#pragma unroll
                for (int r = 0; r < 4; r++) S[m][n][r] = 0.f;

#pragma unroll
        for (int kt = 0; kt < 4; kt++) {
            uint32_t kfh[4][4];
            const uint32_t krow = (lane & 7) + ((lane & 16) ? 8 : 0);
            const uint32_t kcol = kt * 32 + ((lane & 8) ? 16 : 0);
#pragma unroll
            for (int np = 0; np < 4; np++)
                ldsm4(kfh[np], kh_b + (np*16 + krow) * AT_STRIDE + kcol);
#pragma unroll
            for (int m = 0; m < 2; m++)
#pragma unroll
                for (int np = 0; np < 4; np++) {
                    mma_f16(S[m][2*np],   qfr[m][kt], kfh[np]);
                    mma_f16(S[m][2*np+1], qfr[m][kt], kfh[np] + 2);
                }
        }

        uint32_t pa[2][4][4];
#pragma unroll
        for (int m = 0; m < 2; m++)
#pragma unroll
            for (int n = 0; n < 8; n++) {
                float p0 = fast_exp2(S[m][n][0] * SCL2);
                float p1 = fast_exp2(S[m][n][1] * SCL2);
                float p2 = fast_exp2(S[m][n][2] * SCL2);
                float p3 = fast_exp2(S[m][n][3] * SCL2);
                ls[m][0] += p0 + p1;
                ls[m][1] += p2 + p3;
                const int kt = n >> 1, rb = (n & 1) * 2;
                pa[m][kt][rb]     = packh(__float2half_rn(p0), __float2half_rn(p1));
                pa[m][kt][rb + 1] = packh(__float2half_rn(p2), __float2half_rn(p3));
            }

#pragma unroll
        for (int kt = 0; kt < 4; kt++) {
            uint32_t vfh[4][4];
            const uint32_t vrow = kt*16 + (lane & 7) + ((lane & 8) ? 8 : 0);
            const uint32_t vcol = ((lane & 16) ? 16 : 0);
#pragma unroll
            for (int np = 0; np < 4; np++)
                ldsm4t(vfh[np], vh_b + vrow * AT_STRIDE + np*32 + vcol);
#pragma unroll
            for (int m = 0; m < 2; m++)
#pragma unroll
                for (int np = 0; np < 4; np++) {
                    mma_f16(O[m][2*np],   pa[m][kt], vfh[np]);
                    mma_f16(O[m][2*np+1], pa[m][kt], vfh[np] + 2);
                }
        }
    }

    // ---- epilogue ----
#pragma unroll
    for (int m = 0; m < 2; m++)
#pragma unroll
        for (int r = 0; r < 2; r++) {
            ls[m][r] += __shfl_xor_sync(0xffffffffu, ls[m][r], 1);
            ls[m][r] += __shfl_xor_sync(0xffffffffu, ls[m][r], 2);
        }
    const int g = lane >> 2, tg = lane & 3;
#pragma unroll
    for (int m = 0; m < 2; m++) {
#pragma unroll
        for (int rr = 0; rr < 2; rr++) {
            const int row = q0 + wid*32 + m*16 + g + rr*8;
            const float inv = 1.0f / ls[m][rr];
            const size_t rb = ((size_t)b * SEQL + row) * DM + head * DE;
#pragma unroll
            for (int n = 0; n < 8; n++) {
                const int col = n*8 + tg*2;
                *(uint32_t*)(g_oh + rb + col) =
                    packh(__float2half_rn(O[m][n][rr*2]   * inv),
                          __float2half_rn(O[m][n][rr*2+1] * inv));
            }
        }
    }
}

// ---------------- launch ----------------
extern "C" void kernel_launch(void* const* d_in, const int* in_sizes, int n_in,
                              void* d_out, int out_size)
{
    const float* x        = (const float*)d_in[0];
    const float* pos      = (const float*)d_in[1];
    const float* cond     = (const float*)d_in[2];
    const float* w_cond   = (const float*)d_in[3];
    const float* w_qkv    = (const float*)d_in[4];
    const float* qk_scale = (const float*)d_in[5];
    const float* w_out    = (const float*)d_in[6];
    float* out = (float*)d_out;

    __half *p_qkv, *p_xnh, *p_oh, *p_wqh, *p_wql, *p_woh, *p_wol;
    cudaGetSymbolAddress((void**)&p_qkv, g_qkv);
    cudaGetSymbolAddress((void**)&p_xnh, g_xnh);
    cudaGetSymbolAddress((void**)&p_oh,  g_oh);
    cudaGetSymbolAddress((void**)&p_wqh, g_wqh);
    cudaGetSymbolAddress((void**)&p_wql, g_wql);
    cudaGetSymbolAddress((void**)&p_woh, g_woh);
    cudaGetSymbolAddress((void**)&p_wol, g_wol);

    static int s_attr = 0;
    if (!s_attr) {
        cudaFuncSetAttribute(attn_mma_kernel,
                             cudaFuncAttributeMaxDynamicSharedMemorySize, ATTN_SMEM);
        cudaFuncSetAttribute(mma_gemm_kernel<1>,
                             cudaFuncAttributeMaxDynamicSharedMemorySize, GEMM_SMEM);
        cudaFuncSetAttribute(mma_gemm_kernel<0>,
                             cudaFuncAttributeMaxDynamicSharedMemorySize, GEMM_SMEM);
        s_attr = 1;
    }

    cond_partial_kernel<<<dim3(DM/256, NB, 8), 256>>>(cond, w_cond);         // 0
    cond_reduce_kernel<<<NB*DM/256, 256>>>();                                // 1
    fused_pre_kernel<<<FP_RMS + FP_WQ + FP_WO, 256>>>(x, w_qkv, w_out);      // 2
    mma_gemm_kernel<1><<<dim3(3*DM/128, ROWS/128), 256, GEMM_SMEM>>>(        // 3: QKV (profiled)
        p_xnh, p_wqh, p_wql, p_qkv, ROWS, 3*DM, DM);
    qknorm_rope_kernel<<<dim3(ROWS, NH/4), 128>>>(pos, qk_scale);            // 4
    attn_mma_kernel<<<dim3(SEQL/128, NH, NB), 128, ATTN_SMEM>>>();           // 5
    mma_gemm_kernel<0><<<dim3(DM/128, ROWS/128), 256, GEMM_SMEM>>>(          // 6: out
        p_oh, p_woh, p_wol, out, ROWS, DM, DM);
}

// round 10
// speedup vs baseline: 1.2432x; 1.2432x over previous
#include <cuda_runtime.h>
#include <cuda_fp16.h>
#include <math.h>
#include <stdint.h>

// Problem shape: n=2, l=2048, d_model=1024, h=16, e=64
#define NB 2
#define SEQL 2048
#define DM 1024
#define NH 16
#define DE 64
#define ROWS (NB * SEQL)          // 4096

// ---------------- scratch ----------------
__device__ float  g_cwp[8 * NB * DM];         // cond partials
__device__ float  g_cw[NB * DM];
__device__ __half g_xnh[ROWS * DM];
__device__ __half g_qh[NB*NH*SEQL*DE];
__device__ __half g_kh[NB*NH*SEQL*DE];
__device__ __half g_vh[NB*NH*SEQL*DE];
__device__ __half g_oh[ROWS * DM];
__device__ __half g_wqh[DM * 3 * DM], g_wql[DM * 3 * DM];
__device__ __half g_woh[DM * DM],     g_wol[DM * DM];

// ---------------- helpers ----------------
static __device__ __forceinline__ uint32_t smem_u32(const void* p) {
    uint32_t a;
    asm("{ .reg .u64 t; cvta.to.shared.u64 t, %1; cvt.u32.u64 %0, t; }" : "=r"(a) : "l"(p));
    return a;
}
static __device__ __forceinline__ void cpasync16(uint32_t dst, const void* src) {
    asm volatile("cp.async.cg.shared.global [%0], [%1], 16;" :: "r"(dst), "l"(src));
}
#define CP_COMMIT() asm volatile("cp.async.commit_group;" ::: "memory")
#define CP_WAIT1()  asm volatile("cp.async.wait_group 1;"  ::: "memory")
static __device__ __forceinline__ void ldsm4(uint32_t* r, uint32_t a) {
    asm volatile("ldmatrix.sync.aligned.m8n8.x4.shared.b16 {%0,%1,%2,%3}, [%4];"
        : "=r"(r[0]), "=r"(r[1]), "=r"(r[2]), "=r"(r[3]) : "r"(a));
}
static __device__ __forceinline__ void ldsm4t(uint32_t* r, uint32_t a) {
    asm volatile("ldmatrix.sync.aligned.m8n8.x4.trans.shared.b16 {%0,%1,%2,%3}, [%4];"
        : "=r"(r[0]), "=r"(r[1]), "=r"(r[2]), "=r"(r[3]) : "r"(a));
}
static __device__ __forceinline__ void mma_f16(float* c, const uint32_t* a, const uint32_t* b) {
    asm volatile("mma.sync.aligned.m16n8k16.row.col.f32.f16.f16.f32 "
        "{%0,%1,%2,%3}, {%4,%5,%6,%7}, {%8,%9}, {%0,%1,%2,%3};"
        : "+f"(c[0]), "+f"(c[1]), "+f"(c[2]), "+f"(c[3])
        : "r"(a[0]), "r"(a[1]), "r"(a[2]), "r"(a[3]), "r"(b[0]), "r"(b[1]));
}
static __device__ __forceinline__ float fast_exp2(float x) {
    float y; asm("ex2.approx.f32 %0, %1;" : "=f"(y) : "f"(x)); return y;
}
static __device__ __forceinline__ uint32_t packh(__half a, __half b) {
    return (uint32_t)__half_as_ushort(a) | ((uint32_t)__half_as_ushort(b) << 16);
}
static __device__ __forceinline__ uint32_t pack2f(float a, float b) {
    __half2 h = __floats2half2_rn(a, b);
    return *(uint32_t*)&h;
}

// ---------------- cond GEMM: K-split partials + reduce ----------------
__global__ void cond_partial_kernel(const float* __restrict__ cond,
                                    const float* __restrict__ w_cond)
{
    __shared__ float cs[128];
    const int n  = blockIdx.y;
    const int ks = blockIdx.z;
    if (threadIdx.x < 128)
        cs[threadIdx.x] = cond[n * DM + ks * 128 + threadIdx.x];
    __syncthreads();
    const int j = blockIdx.x * blockDim.x + threadIdx.x;
    float acc = 0.f;
#pragma unroll 8
    for (int k = 0; k < 128; k++)
        acc = fmaf(cs[k], w_cond[(size_t)(ks * 128 + k) * DM + j], acc);
    g_cwp[(ks * NB + n) * DM + j] = acc;
}
__global__ void cond_reduce_kernel()
{
    const int i = blockIdx.x * blockDim.x + threadIdx.x;
    const int n = i / DM, j = i % DM;
    float s = 1.0f;
#pragma unroll
    for (int ks = 0; ks < 8; ks++)
        s += g_cwp[(ks * NB + n) * DM + j];
    g_cw[i] = s;
}

// ---------------- fused: rmsnorm(x) + split(w_qkv) + split(w_out) ----------------
#define FP_RMS   ROWS
#define FP_WQ    (DM * 3 * DM / 256)     // 12288
#define FP_WO    (DM * DM / 256)         // 4096
__global__ void fused_pre_kernel(const float* __restrict__ x,
                                 const float* __restrict__ w_qkv,
                                 const float* __restrict__ w_out)
{
    const int b = blockIdx.x;
    const int t = threadIdx.x;
    if (b < FP_RMS) {
        const int row = b;
        const int n = row / SEQL;
        float4 v = *(const float4*)(x + (size_t)row * DM + t * 4);
        float ss = v.x * v.x + v.y * v.y + v.z * v.z + v.w * v.w;
#pragma unroll
        for (int o = 16; o > 0; o >>= 1)
            ss += __shfl_xor_sync(0xffffffffu, ss, o);
        __shared__ float ws[8];
        if ((t & 31) == 0) ws[t >> 5] = ss;
        __syncthreads();
        float tot = ws[0]+ws[1]+ws[2]+ws[3]+ws[4]+ws[5]+ws[6]+ws[7];
        float rinv = rsqrtf(tot * (1.0f / DM) + 1e-6f);
        float4 cwv = *(const float4*)(g_cw + n * DM + t * 4);
        size_t base = (size_t)row * DM + t * 4;
        *(uint32_t*)(g_xnh + base)     = pack2f(v.x * cwv.x * rinv, v.y * cwv.y * rinv);
        *(uint32_t*)(g_xnh + base + 2) = pack2f(v.z * cwv.z * rinv, v.w * cwv.w * rinv);
    } else if (b < FP_RMS + FP_WQ) {
        int i = (b - FP_RMS) * 256 + t;
        float v = w_qkv[i];
        __half hh = __float2half_rn(v);
        g_wqh[i] = hh;
        g_wql[i] = __float2half_rn(v - __half2float(hh));
    } else {
        int i = (b - FP_RMS - FP_WQ) * 256 + t;
        float v = w_out[i];
        __half hh = __float2half_rn(v);
        g_woh[i] = hh;
        g_wol[i] = __float2half_rn(v - __half2float(hh));
    }
}

// ---------------- GEMM core: BM=128, BN=128, BK=32, 3-stage (R8 config) ----------------
#define GM_ASTRIDE 80
#define GM_BSTRIDE 272
#define GM_A_SZ (128 * GM_ASTRIDE)            // 10240
#define GM_B_SZ (32 * GM_BSTRIDE)             // 8704
#define GM_BUF (GM_A_SZ + 2*GM_B_SZ)          // 27648
#define GEMM_SMEM (3 * GM_BUF)                // 82944

static __device__ __forceinline__ void gemm_load(uint32_t smb, int bufi,
    const __half* Ah, const __half* Bh, const __half* Bl,
    int m0, int n0, int k0, int K, int N, int tid)
{
    uint32_t base = smb + bufi * GM_BUF;
    const int ar = tid >> 1, ac = (tid & 1) * 16;
    const __half* pah = Ah + (size_t)(m0 + ar) * K + k0 + ac;
    cpasync16(base + ar*GM_ASTRIDE + ac*2,      pah);
    cpasync16(base + ar*GM_ASTRIDE + ac*2 + 16, pah + 8);
    const int br = tid >> 3, bc = (tid & 7) * 16;
    const __half* pbh = Bh + (size_t)(k0 + br) * N + n0 + bc;
    const __half* pbl = Bl + (size_t)(k0 + br) * N + n0 + bc;
    uint32_t bb = base + GM_A_SZ;
    cpasync16(bb + br*GM_BSTRIDE + bc*2,      pbh);
    cpasync16(bb + br*GM_BSTRIDE + bc*2 + 16, pbh + 8);
    cpasync16(bb + GM_B_SZ + br*GM_BSTRIDE + bc*2,      pbl);
    cpasync16(bb + GM_B_SZ + br*GM_BSTRIDE + bc*2 + 16, pbl + 8);
}

// mainloop shared by both GEMMs (computes acc for this thread's warp tile)
#define GEMM_MAINLOOP(Ah, Bh, Bl, K, N)                                         \
    const int nk = (K) / 32;                                                    \
    gemm_load(smb, 0, Ah, Bh, Bl, m0, n0, 0, K, N, tid);                        \
    CP_COMMIT();                                                                \
    gemm_load(smb, 1, Ah, Bh, Bl, m0, n0, 32, K, N, tid);                       \
    CP_COMMIT();                                                                \
    for (int s = 0; s < nk; s++) {                                              \
        CP_WAIT1();                                                             \
        __syncthreads();                                                        \
        if (s + 2 < nk)                                                         \
            gemm_load(smb, (s + 2) % 3, Ah, Bh, Bl, m0, n0, (s + 2) * 32, K, N, tid); \
        CP_COMMIT();                                                            \
        uint32_t base = smb + (s % 3) * GM_BUF;                                 \
        uint32_t a_h = base;                                                    \
        uint32_t b_h = base + GM_A_SZ, b_l = b_h + GM_B_SZ;                     \
        _Pragma("unroll")                                                       \
        for (int kt = 0; kt < 2; kt++) {                                        \
            uint32_t bfh[4][4], bfl[4][4];                                      \
            const uint32_t brow = kt * 16 + (lane & 7) + ((lane & 8) ? 8 : 0);  \
            const uint32_t bcol = wn * 2 + ((lane & 16) ? 16 : 0);              \
            _Pragma("unroll")                                                   \
            for (int np = 0; np < 4; np++) {                                    \
                ldsm4t(bfh[np], b_h + brow * GM_BSTRIDE + bcol + np * 32);      \
                ldsm4t(bfl[np], b_l + brow * GM_BSTRIDE + bcol + np * 32);      \
            }                                                                   \
            _Pragma("unroll")                                                   \
            for (int m = 0; m < 2; m++) {                                       \
                uint32_t afh[4];                                                \
                const uint32_t arow = wm + m * 16 + (lane & 15);                \
                const uint32_t acol = kt * 32 + ((lane & 16) ? 16 : 0);         \
                ldsm4(afh, a_h + arow * GM_ASTRIDE + acol);                     \
                _Pragma("unroll")                                               \
                for (int np = 0; np < 4; np++) {                                \
                    mma_f16(acc[m][2*np],   afh, bfh[np]);                      \
                    mma_f16(acc[m][2*np+1], afh, bfh[np] + 2);                  \
                    mma_f16(acc[m][2*np],   afh, bfl[np]);                      \
                    mma_f16(acc[m][2*np+1], afh, bfl[np] + 2);                  \
                }                                                               \
            }                                                                   \
        }                                                                       \
    }

// ---------------- QKV GEMM with fused qk-rmsnorm + rope epilogue ----------------
// C row = token (nb,l); cols: [0,1024) Q, [1024,2048) K, [2048,3072) V.
// A warp's 64-col tile = exactly one head; rotary pair (c, c+32) = acc[m][n], acc[m][n+4].
__global__ __launch_bounds__(256, 2) void qkv_gemm_kernel(
    const __half* __restrict__ Ah,
    const __half* __restrict__ Bh, const __half* __restrict__ Bl,
    const float* __restrict__ pos, const float* __restrict__ qk_scale)
{
    extern __shared__ char sm[];
    const uint32_t smb = smem_u32(sm);
    const int tid = threadIdx.x, lane = tid & 31, wid = tid >> 5;
    const int m0 = blockIdx.y * 128, n0 = blockIdx.x * 128;
    const int wm = (wid & 3) * 32, wn = (wid >> 2) * 64;
    const int K = DM, N = 3 * DM;

    float acc[2][8][4];
#pragma unroll
    for (int m = 0; m < 2; m++)
#pragma unroll
        for (int n = 0; n < 8; n++)
#pragma unroll
            for (int r = 0; r < 4; r++) acc[m][n][r] = 0.f;

    GEMM_MAINLOOP(Ah, Bh, Bl, K, N)

    const int g = lane >> 2, tg = lane & 3;
    const int region = n0 >> 10;                    // 0 Q, 1 K, 2 V
    const int head = ((n0 + wn) & 1023) >> 6;
    const size_t hb = (size_t)head * SEQL * DE;

    if (region == 2) {
        // V: plain fp16 store into (n,h,l,e)
#pragma unroll
        for (int m = 0; m < 2; m++)
#pragma unroll
            for (int rr = 0; rr < 2; rr++) {
                const int row = m0 + wm + m*16 + g + rr*8;
                const int nb = row >> 11, l = row & (SEQL - 1);
                const size_t ob = (size_t)nb * NH * SEQL * DE + hb + (size_t)l * DE;
#pragma unroll
                for (int n = 0; n < 8; n++) {
                    const int c = n*8 + tg*2;
                    *(uint32_t*)(g_vh + ob + c) = pack2f(acc[m][n][rr*2], acc[m][n][rr*2+1]);
                }
            }
    } else {
        __half* dst = region ? g_kh : g_qh;
        const float sc = expf(0.5f * fminf(qk_scale[head], 4.6051701860f) - 1.0397207708f);
        // per-column freqs (loop-invariant over m, rr)
        float fr0[4], fr1[4];
#pragma unroll
        for (int n = 0; n < 4; n++) {
            const int c0 = n*8 + tg*2;
            fr0[n] = expf(1.14472988584940017f + (float)((c0 & 15) * 16 + head) * (2.30258509299404568f / 256.0f));
            fr1[n] = expf(1.14472988584940017f + (float)(((c0+1) & 15) * 16 + head) * (2.30258509299404568f / 256.0f));
        }
#pragma unroll
        for (int m = 0; m < 2; m++)
#pragma unroll
            for (int rr = 0; rr < 2; rr++) {
                // row sumsq over all 64 cols (this lane holds 16, tg-group holds 64)
                float ss = 0.f;
#pragma unroll
                for (int n = 0; n < 8; n++) {
                    float a0 = acc[m][n][rr*2], a1 = acc[m][n][rr*2+1];
                    ss += a0*a0 + a1*a1;
                }
                ss += __shfl_xor_sync(0xffffffffu, ss, 1);
                ss += __shfl_xor_sync(0xffffffffu, ss, 2);
                const float rinv = sc * rsqrtf(ss * (1.0f / DE) + 1e-6f);

                const int row = m0 + wm + m*16 + g + rr*8;
                const int nb = row >> 11, l = row & (SEQL - 1);
                const size_t ob = (size_t)nb * NH * SEQL * DE + hb + (size_t)l * DE;
#pragma unroll
                for (int n = 0; n < 4; n++) {
                    const int c0 = n*8 + tg*2;
                    const float pv = pos[(size_t)row * 2 + (c0 >> 4)];
                    float s0, cth0, s1, cth1;
                    __sincosf(pv * fr0[n], &s0, &cth0);
                    __sincosf(pv * fr1[n], &s1, &cth1);
                    const float x1a = acc[m][n][rr*2]     * rinv;
                    const float x1b = acc[m][n][rr*2+1]   * rinv;
                    const float x2a = acc[m][n+4][rr*2]   * rinv;
                    const float x2b = acc[m][n+4][rr*2+1] * rinv;
                    *(uint32_t*)(dst + ob + c0)      = pack2f(x1a*cth0 - x2a*s0, x1b*cth1 - x2b*s1);
                    *(uint32_t*)(dst + ob + c0 + 32) = pack2f(x2a*cth0 + x1a*s0, x2b*cth1 + x1b*s1);
                }
            }
    }
}

// ---------------- out GEMM (fp32 output) ----------------
__global__ __launch_bounds__(256, 2) void out_gemm_kernel(
    const __half* __restrict__ Ah,
    const __half* __restrict__ Bh, const __half* __restrict__ Bl,
    float* __restrict__ C)
{
    extern __shared__ char sm[];
    const uint32_t smb = smem_u32(sm);
    const int tid = threadIdx.x, lane = tid & 31, wid = tid >> 5;
    const int m0 = blockIdx.y * 128, n0 = blockIdx.x * 128;
    const int wm = (wid & 3) * 32, wn = (wid >> 2) * 64;
    const int K = DM, N = DM;

    float acc[2][8][4];
#pragma unroll
    for (int m = 0; m < 2; m++)
#pragma unroll
        for (int n = 0; n < 8; n++)
#pragma unroll
            for (int r = 0; r < 4; r++) acc[m][n][r] = 0.f;

    GEMM_MAINLOOP(Ah, Bh, Bl, K, N)

    const int g = lane >> 2, tg = lane & 3;
#pragma unroll
    for (int m = 0; m < 2; m++)
#pragma unroll
        for (int rr = 0; rr < 2; rr++) {
            int row = m0 + wm + m * 16 + g + rr * 8;
#pragma unroll
            for (int n = 0; n < 8; n++) {
                int col = n0 + wn + n * 8 + tg * 2;
                *(float2*)(C + (size_t)row * N + col) =
                    make_float2(acc[m][n][rr*2], acc[m][n][rr*2+1]);
            }
        }
}

// ---------------- attention via mma.sync (fp16 QKV, fp32 accum), 3-stage ----------------
#define AT_STRIDE 144
#define AT_QH 0
#define AT_KV0 (128 * AT_STRIDE)              // 18432
#define AT_ARR (64 * AT_STRIDE)               // 9216 per array
#define AT_BUF (2 * AT_ARR)                   // 18432 (Kh, Vh)
#define NKT (SEQL / 64)                       // 32
#define ATTN_SMEM (AT_KV0 + 3 * AT_BUF)       // 73728

static __device__ __forceinline__ void attn_load_kv(uint32_t smb, size_t bh,
                                                    int tid, int t, int bufi)
{
    const int k0 = t * 64;
    const int r  = tid >> 1;
    const int hc = (tid & 1) * 32;
    uint32_t base = smb + AT_KV0 + bufi * AT_BUF + r * AT_STRIDE + hc * 2;
    const __half* s0 = g_kh + (bh + k0 + r) * DE + hc;
    const __half* s1 = g_vh + (bh + k0 + r) * DE + hc;
#pragma unroll
    for (int c = 0; c < 4; c++) {
        cpasync16(base + 0*AT_ARR + c*16, s0 + c*8);
        cpasync16(base + 1*AT_ARR + c*16, s1 + c*8);
    }
}

__global__ __launch_bounds__(128) void attn_mma_kernel()
{
    extern __shared__ char sm[];
    const uint32_t smb = smem_u32(sm);
    const int tid = threadIdx.x, lane = tid & 31, wid = tid >> 5;
    const int q0 = blockIdx.x * 128, head = blockIdx.y, b = blockIdx.z;
    const size_t bh = (size_t)(b * NH + head) * SEQL;
    const float SCL2 = 0.18033688011112042f;   // log2(e)/8

    {
        const __half* qh = g_qh + (bh + q0 + tid) * DE;
        uint32_t dh = smb + AT_QH + tid * AT_STRIDE;
#pragma unroll
        for (int c = 0; c < 8; c++)
            cpasync16(dh + c*16, qh + c*8);
    }
    attn_load_kv(smb, bh, tid, 0, 0);
    CP_COMMIT();
    attn_load_kv(smb, bh, tid, 1, 1);
    CP_COMMIT();
    CP_WAIT1();                 // Q + kv0 resident
    __syncthreads();

    uint32_t qfr[2][4][4];
#pragma unroll
    for (int m = 0; m < 2; m++)
#pragma unroll
        for (int kt = 0; kt < 4; kt++) {
            const uint32_t qrow = wid*32 + m*16 + (lane & 15);
            const uint32_t qcol = kt * 32 + ((lane & 16) ? 16 : 0);
            ldsm4(qfr[m][kt], smb + AT_QH + qrow * AT_STRIDE + qcol);
        }

    float O[2][8][4];
#pragma unroll
    for (int m = 0; m < 2; m++)
#pragma unroll
        for (int n = 0; n < 8; n++)
#pragma unroll
            for (int r = 0; r < 4; r++) O[m][n][r] = 0.f;
    float ls[2][2] = {{0.f, 0.f}, {0.f, 0.f}};

    for (int t = 0; t < NKT; t++) {
        CP_WAIT1();                 // kv(t) resident, kv(t+1) in flight
        __syncthreads();
        if (t + 2 < NKT)
            attn_load_kv(smb, bh, tid, t + 2, (t + 2) % 3);
        CP_COMMIT();

        uint32_t kb  = smb + AT_KV0 + (t % 3) * AT_BUF;
        uint32_t kh_b = kb, vh_b = kb + AT_ARR;

        float S[2][8][4];
#pragma unroll
        for (int m = 0; m < 2; m++)
#pragma unroll
            for (int n = 0; n < 8; n++)
#pragma unroll
                for (int r = 0; r < 4; r++) S[m][n][r] = 0.f;

#pragma unroll
        for (int kt = 0; kt < 4; kt++) {
            uint32_t kfh[4][4];
            const uint32_t krow = (lane & 7) + ((lane & 16) ? 8 : 0);
            const uint32_t kcol = kt * 32 + ((lane & 8) ? 16 : 0);
#pragma unroll
            for (int np = 0; np < 4; np++)
                ldsm4(kfh[np], kh_b + (np*16 + krow) * AT_STRIDE + kcol);
#pragma unroll
            for (int m = 0; m < 2; m++)
#pragma unroll
                for (int np = 0; np < 4; np++) {
                    mma_f16(S[m][2*np],   qfr[m][kt], kfh[np]);
                    mma_f16(S[m][2*np+1], qfr[m][kt], kfh[np] + 2);
                }
        }

        uint32_t pa[2][4][4];
#pragma unroll
        for (int m = 0; m < 2; m++)
#pragma unroll
            for (int n = 0; n < 8; n++) {
                float p0 = fast_exp2(S[m][n][0] * SCL2);
                float p1 = fast_exp2(S[m][n][1] * SCL2);
                float p2 = fast_exp2(S[m][n][2] * SCL2);
                float p3 = fast_exp2(S[m][n][3] * SCL2);
                ls[m][0] += p0 + p1;
                ls[m][1] += p2 + p3;
                const int kt = n >> 1, rb = (n & 1) * 2;
                pa[m][kt][rb]     = pack2f(p0, p1);
                pa[m][kt][rb + 1] = pack2f(p2, p3);
            }

#pragma unroll
        for (int kt = 0; kt < 4; kt++) {
            uint32_t vfh[4][4];
            const uint32_t vrow = kt*16 + (lane & 7) + ((lane & 8) ? 8 : 0);
            const uint32_t vcol = ((lane & 16) ? 16 : 0);
#pragma unroll
            for (int np = 0; np < 4; np++)
                ldsm4t(vfh[np], vh_b + vrow * AT_STRIDE + np*32 + vcol);
#pragma unroll
            for (int m = 0; m < 2; m++)
#pragma unroll
                for (int np = 0; np < 4; np++) {
                    mma_f16(O[m][2*np],   pa[m][kt], vfh[np]);
                    mma_f16(O[m][2*np+1], pa[m][kt], vfh[np] + 2);
                }
        }
    }

    // ---- epilogue ----
#pragma unroll
    for (int m = 0; m < 2; m++)
#pragma unroll
        for (int r = 0; r < 2; r++) {
            ls[m][r] += __shfl_xor_sync(0xffffffffu, ls[m][r], 1);
            ls[m][r] += __shfl_xor_sync(0xffffffffu, ls[m][r], 2);
        }
    const int g = lane >> 2, tg = lane & 3;
#pragma unroll
    for (int m = 0; m < 2; m++) {
#pragma unroll
        for (int rr = 0; rr < 2; rr++) {
            const int row = q0 + wid*32 + m*16 + g + rr*8;
            const float inv = 1.0f / ls[m][rr];
            const size_t rb = ((size_t)b * SEQL + row) * DM + head * DE;
#pragma unroll
            for (int n = 0; n < 8; n++) {
                const int col = n*8 + tg*2;
                *(uint32_t*)(g_oh + rb + col) =
                    pack2f(O[m][n][rr*2] * inv, O[m][n][rr*2+1] * inv);
            }
        }
    }
}

// ---------------- launch ----------------
extern "C" void kernel_launch(void* const* d_in, const int* in_sizes, int n_in,
                              void* d_out, int out_size)
{
    const float* x        = (const float*)d_in[0];
    const float* pos      = (const float*)d_in[1];
    const float* cond     = (const float*)d_in[2];
    const float* w_cond   = (const float*)d_in[3];
    const float* w_qkv    = (const float*)d_in[4];
    const float* qk_scale = (const float*)d_in[5];
    const float* w_out    = (const float*)d_in[6];
    float* out = (float*)d_out;

    __half *p_xnh, *p_oh, *p_wqh, *p_wql, *p_woh, *p_wol;
    cudaGetSymbolAddress((void**)&p_xnh, g_xnh);
    cudaGetSymbolAddress((void**)&p_oh,  g_oh);
    cudaGetSymbolAddress((void**)&p_wqh, g_wqh);
    cudaGetSymbolAddress((void**)&p_wql, g_wql);
    cudaGetSymbolAddress((void**)&p_woh, g_woh);
    cudaGetSymbolAddress((void**)&p_wol, g_wol);

    static int s_attr = 0;
    if (!s_attr) {
        cudaFuncSetAttribute(attn_mma_kernel,
                             cudaFuncAttributeMaxDynamicSharedMemorySize, ATTN_SMEM);
        cudaFuncSetAttribute(qkv_gemm_kernel,
                             cudaFuncAttributeMaxDynamicSharedMemorySize, GEMM_SMEM);
        cudaFuncSetAttribute(out_gemm_kernel,
                             cudaFuncAttributeMaxDynamicSharedMemorySize, GEMM_SMEM);
        s_attr = 1;
    }

    cond_partial_kernel<<<dim3(DM/256, NB, 8), 256>>>(cond, w_cond);         // 0
    cond_reduce_kernel<<<NB*DM/256, 256>>>();                                // 1
    fused_pre_kernel<<<FP_RMS + FP_WQ + FP_WO, 256>>>(x, w_qkv, w_out);      // 2
    qkv_gemm_kernel<<<dim3(3*DM/128, ROWS/128), 256, GEMM_SMEM>>>(           // 3 (profiled)
        p_xnh, p_wqh, p_wql, pos, qk_scale);
    attn_mma_kernel<<<dim3(SEQL/128, NH, NB), 128, ATTN_SMEM>>>();           // 4
    out_gemm_kernel<<<dim3(DM/128, ROWS/128), 256, GEMM_SMEM>>>(             // 5
        p_oh, p_woh, p_wol, out);
}

// round 11
// speedup vs baseline: 1.2738x; 1.0246x over previous
#include <cuda_runtime.h>
#include <cuda_fp16.h>
#include <math.h>
#include <stdint.h>

// Problem shape: n=2, l=2048, d_model=1024, h=16, e=64
#define NB 2
#define SEQL 2048
#define DM 1024
#define NH 16
#define DE 64
#define ROWS (NB * SEQL)          // 4096

// ---------------- scratch ----------------
__device__ float  g_cwp[8 * NB * DM];         // cond partials
__device__ float  g_cw[NB * DM];
__device__ __half g_xnh[ROWS * DM];
__device__ __half g_qh[NB*NH*SEQL*DE];
__device__ __half g_kh[NB*NH*SEQL*DE];
__device__ __half g_vh[NB*NH*SEQL*DE];
__device__ __half g_oh[ROWS * DM];
__device__ __half g_wqh[DM * 3 * DM], g_wql[DM * 3 * DM];
__device__ __half g_woh[DM * DM],     g_wol[DM * DM];

// ---------------- helpers ----------------
static __device__ __forceinline__ uint32_t smem_u32(const void* p) {
    uint32_t a;
    asm("{ .reg .u64 t; cvta.to.shared.u64 t, %1; cvt.u32.u64 %0, t; }" : "=r"(a) : "l"(p));
    return a;
}
static __device__ __forceinline__ void cpasync16(uint32_t dst, const void* src) {
    asm volatile("cp.async.cg.shared.global [%0], [%1], 16;" :: "r"(dst), "l"(src));
}
#define CP_COMMIT() asm volatile("cp.async.commit_group;" ::: "memory")
#define CP_WAIT1()  asm volatile("cp.async.wait_group 1;"  ::: "memory")
static __device__ __forceinline__ void ldsm4(uint32_t* r, uint32_t a) {
    asm volatile("ldmatrix.sync.aligned.m8n8.x4.shared.b16 {%0,%1,%2,%3}, [%4];"
        : "=r"(r[0]), "=r"(r[1]), "=r"(r[2]), "=r"(r[3]) : "r"(a));
}
static __device__ __forceinline__ void ldsm4t(uint32_t* r, uint32_t a) {
    asm volatile("ldmatrix.sync.aligned.m8n8.x4.trans.shared.b16 {%0,%1,%2,%3}, [%4];"
        : "=r"(r[0]), "=r"(r[1]), "=r"(r[2]), "=r"(r[3]) : "r"(a));
}
static __device__ __forceinline__ void mma_f16(float* c, const uint32_t* a, const uint32_t* b) {
    asm volatile("mma.sync.aligned.m16n8k16.row.col.f32.f16.f16.f32 "
        "{%0,%1,%2,%3}, {%4,%5,%6,%7}, {%8,%9}, {%0,%1,%2,%3};"
        : "+f"(c[0]), "+f"(c[1]), "+f"(c[2]), "+f"(c[3])
        : "r"(a[0]), "r"(a[1]), "r"(a[2]), "r"(a[3]), "r"(b[0]), "r"(b[1]));
}
static __device__ __forceinline__ uint32_t exp2_h2(float a, float b) {
    __half2 h = __floats2half2_rn(a, b);
    uint32_t r = *(uint32_t*)&h, o;
    asm("ex2.approx.f16x2 %0, %1;" : "=r"(o) : "r"(r));
    return o;
}
static __device__ __forceinline__ uint32_t pack2f(float a, float b) {
    __half2 h = __floats2half2_rn(a, b);
    return *(uint32_t*)&h;
}

// ---------------- cond GEMM: K-split partials + reduce ----------------
__global__ void cond_partial_kernel(const float* __restrict__ cond,
                                    const float* __restrict__ w_cond)
{
    __shared__ float cs[128];
    const int n  = blockIdx.y;
    const int ks = blockIdx.z;
    if (threadIdx.x < 128)
        cs[threadIdx.x] = cond[n * DM + ks * 128 + threadIdx.x];
    __syncthreads();
    const int j = blockIdx.x * blockDim.x + threadIdx.x;
    float acc = 0.f;
#pragma unroll 8
    for (int k = 0; k < 128; k++)
        acc = fmaf(cs[k], w_cond[(size_t)(ks * 128 + k) * DM + j], acc);
    g_cwp[(ks * NB + n) * DM + j] = acc;
}
__global__ void cond_reduce_kernel()
{
    const int i = blockIdx.x * blockDim.x + threadIdx.x;
    const int n = i / DM, j = i % DM;
    float s = 1.0f;
#pragma unroll
    for (int ks = 0; ks < 8; ks++)
        s += g_cwp[(ks * NB + n) * DM + j];
    g_cw[i] = s;
}

// ---------------- fused: rmsnorm(x) + split(w_qkv) + split(w_out) ----------------
#define FP_RMS   ROWS
#define FP_WQ    (DM * 3 * DM / 256)     // 12288
#define FP_WO    (DM * DM / 256)         // 4096
__global__ void fused_pre_kernel(const float* __restrict__ x,
                                 const float* __restrict__ w_qkv,
                                 const float* __restrict__ w_out)
{
    const int b = blockIdx.x;
    const int t = threadIdx.x;
    if (b < FP_RMS) {
        const int row = b;
        const int n = row / SEQL;
        float4 v = *(const float4*)(x + (size_t)row * DM + t * 4);
        float ss = v.x * v.x + v.y * v.y + v.z * v.z + v.w * v.w;
#pragma unroll
        for (int o = 16; o > 0; o >>= 1)
            ss += __shfl_xor_sync(0xffffffffu, ss, o);
        __shared__ float ws[8];
        if ((t & 31) == 0) ws[t >> 5] = ss;
        __syncthreads();
        float tot = ws[0]+ws[1]+ws[2]+ws[3]+ws[4]+ws[5]+ws[6]+ws[7];
        float rinv = rsqrtf(tot * (1.0f / DM) + 1e-6f);
        float4 cwv = *(const float4*)(g_cw + n * DM + t * 4);
        size_t base = (size_t)row * DM + t * 4;
        *(uint32_t*)(g_xnh + base)     = pack2f(v.x * cwv.x * rinv, v.y * cwv.y * rinv);
        *(uint32_t*)(g_xnh + base + 2) = pack2f(v.z * cwv.z * rinv, v.w * cwv.w * rinv);
    } else if (b < FP_RMS + FP_WQ) {
        int i = (b - FP_RMS) * 256 + t;
        float v = w_qkv[i];
        __half hh = __float2half_rn(v);
        g_wqh[i] = hh;
        g_wql[i] = __float2half_rn(v - __half2float(hh));
    } else {
        int i = (b - FP_RMS - FP_WQ) * 256 + t;
        float v = w_out[i];
        __half hh = __float2half_rn(v);
        g_woh[i] = hh;
        g_wol[i] = __float2half_rn(v - __half2float(hh));
    }
}

// ---------------- GEMM core: BM=128, BN=128, BK=32, 3-stage ----------------
#define GM_ASTRIDE 80
#define GM_BSTRIDE 272
#define GM_A_SZ (128 * GM_ASTRIDE)            // 10240
#define GM_B_SZ (32 * GM_BSTRIDE)             // 8704
#define GM_BUF (GM_A_SZ + 2*GM_B_SZ)          // 27648
#define GEMM_SMEM (3 * GM_BUF)                // 82944

static __device__ __forceinline__ void gemm_load(uint32_t smb, int bufi,
    const __half* Ah, const __half* Bh, const __half* Bl,
    int m0, int n0, int k0, int K, int N, int tid)
{
    uint32_t base = smb + bufi * GM_BUF;
    const int ar = tid >> 1, ac = (tid & 1) * 16;
    const __half* pah = Ah + (size_t)(m0 + ar) * K + k0 + ac;
    cpasync16(base + ar*GM_ASTRIDE + ac*2,      pah);
    cpasync16(base + ar*GM_ASTRIDE + ac*2 + 16, pah + 8);
    const int br = tid >> 3, bc = (tid & 7) * 16;
    const __half* pbh = Bh + (size_t)(k0 + br) * N + n0 + bc;
    const __half* pbl = Bl + (size_t)(k0 + br) * N + n0 + bc;
    uint32_t bb = base + GM_A_SZ;
    cpasync16(bb + br*GM_BSTRIDE + bc*2,      pbh);
    cpasync16(bb + br*GM_BSTRIDE + bc*2 + 16, pbh + 8);
    cpasync16(bb + GM_B_SZ + br*GM_BSTRIDE + bc*2,      pbl);
    cpasync16(bb + GM_B_SZ + br*GM_BSTRIDE + bc*2 + 16, pbl + 8);
}

#define GEMM_MAINLOOP(Ah, Bh, Bl, K, N)                                         \
    const int nk = (K) / 32;                                                    \
    gemm_load(smb, 0, Ah, Bh, Bl, m0, n0, 0, K, N, tid);                        \
    CP_COMMIT();                                                                \
    gemm_load(smb, 1, Ah, Bh, Bl, m0, n0, 32, K, N, tid);                       \
    CP_COMMIT();                                                                \
    for (int s = 0; s < nk; s++) {                                              \
        CP_WAIT1();                                                             \
        __syncthreads();                                                        \
        if (s + 2 < nk)                                                         \
            gemm_load(smb, (s + 2) % 3, Ah, Bh, Bl, m0, n0, (s + 2) * 32, K, N, tid); \
        CP_COMMIT();                                                            \
        uint32_t base = smb + (s % 3) * GM_BUF;                                 \
        uint32_t a_h = base;                                                    \
        uint32_t b_h = base + GM_A_SZ, b_l = b_h + GM_B_SZ;                     \
        _Pragma("unroll")                                                       \
        for (int kt = 0; kt < 2; kt++) {                                        \
            uint32_t bfh[4][4], bfl[4][4];                                      \
            const uint32_t brow = kt * 16 + (lane & 7) + ((lane & 8) ? 8 : 0);  \
            const uint32_t bcol = wn * 2 + ((lane & 16) ? 16 : 0);              \
            _Pragma("unroll")                                                   \
            for (int np = 0; np < 4; np++) {                                    \
                ldsm4t(bfh[np], b_h + brow * GM_BSTRIDE + bcol + np * 32);      \
                ldsm4t(bfl[np], b_l + brow * GM_BSTRIDE + bcol + np * 32);      \
            }                                                                   \
            _Pragma("unroll")                                                   \
            for (int m = 0; m < 2; m++) {                                       \
                uint32_t afh[4];                                                \
                const uint32_t arow = wm + m * 16 + (lane & 15);                \
                const uint32_t acol = kt * 32 + ((lane & 16) ? 16 : 0);         \
                ldsm4(afh, a_h + arow * GM_ASTRIDE + acol);                     \
                _Pragma("unroll")                                               \
                for (int np = 0; np < 4; np++) {                                \
                    mma_f16(acc[m][2*np],   afh, bfh[np]);                      \
                    mma_f16(acc[m][2*np+1], afh, bfh[np] + 2);                  \
                    mma_f16(acc[m][2*np],   afh, bfl[np]);                      \
                    mma_f16(acc[m][2*np+1], afh, bfl[np] + 2);                  \
                }                                                               \
            }                                                                   \
        }                                                                       \
    }

// ---------------- QKV GEMM with fused qk-rmsnorm + rope epilogue ----------------
// Q additionally pre-scaled by log2(e)/8 so attention scores come out of the
// S-MMA already in log2 domain.
__global__ __launch_bounds__(256, 2) void qkv_gemm_kernel(
    const __half* __restrict__ Ah,
    const __half* __restrict__ Bh, const __half* __restrict__ Bl,
    const float* __restrict__ pos, const float* __restrict__ qk_scale)
{
    extern __shared__ char sm[];
    const uint32_t smb = smem_u32(sm);
    const int tid = threadIdx.x, lane = tid & 31, wid = tid >> 5;
    const int m0 = blockIdx.y * 128, n0 = blockIdx.x * 128;
    const int wm = (wid & 3) * 32, wn = (wid >> 2) * 64;
    const int K = DM, N = 3 * DM;

    float acc[2][8][4];
#pragma unroll
    for (int m = 0; m < 2; m++)
#pragma unroll
        for (int n = 0; n < 8; n++)
#pragma unroll
            for (int r = 0; r < 4; r++) acc[m][n][r] = 0.f;

    GEMM_MAINLOOP(Ah, Bh, Bl, K, N)

    const int g = lane >> 2, tg = lane & 3;
    const int region = n0 >> 10;                    // 0 Q, 1 K, 2 V
    const int head = ((n0 + wn) & 1023) >> 6;
    const size_t hb = (size_t)head * SEQL * DE;

    if (region == 2) {
#pragma unroll
        for (int m = 0; m < 2; m++)
#pragma unroll
            for (int rr = 0; rr < 2; rr++) {
                const int row = m0 + wm + m*16 + g + rr*8;
                const int nb = row >> 11, l = row & (SEQL - 1);
                const size_t ob = (size_t)nb * NH * SEQL * DE + hb + (size_t)l * DE;
#pragma unroll
                for (int n = 0; n < 8; n++) {
                    const int c = n*8 + tg*2;
                    *(uint32_t*)(g_vh + ob + c) = pack2f(acc[m][n][rr*2], acc[m][n][rr*2+1]);
                }
            }
    } else {
        __half* dst = region ? g_kh : g_qh;
        float sc = expf(0.5f * fminf(qk_scale[head], 4.6051701860f) - 1.0397207708f);
        if (region == 0) sc *= 0.18033688011112042f;   // log2(e)/8 folded into Q
        float fr0[4], fr1[4];
#pragma unroll
        for (int n = 0; n < 4; n++) {
            const int c0 = n*8 + tg*2;
            fr0[n] = expf(1.14472988584940017f + (float)((c0 & 15) * 16 + head) * (2.30258509299404568f / 256.0f));
            fr1[n] = expf(1.14472988584940017f + (float)(((c0+1) & 15) * 16 + head) * (2.30258509299404568f / 256.0f));
        }
#pragma unroll
        for (int m = 0; m < 2; m++)
#pragma unroll
            for (int rr = 0; rr < 2; rr++) {
                float ss = 0.f;
#pragma unroll
                for (int n = 0; n < 8; n++) {
                    float a0 = acc[m][n][rr*2], a1 = acc[m][n][rr*2+1];
                    ss += a0*a0 + a1*a1;
                }
                ss += __shfl_xor_sync(0xffffffffu, ss, 1);
                ss += __shfl_xor_sync(0xffffffffu, ss, 2);
                const float rinv = sc * rsqrtf(ss * (1.0f / DE) + 1e-6f);

                const int row = m0 + wm + m*16 + g + rr*8;
                const int nb = row >> 11, l = row & (SEQL - 1);
                const size_t ob = (size_t)nb * NH * SEQL * DE + hb + (size_t)l * DE;
#pragma unroll
                for (int n = 0; n < 4; n++) {
                    const int c0 = n*8 + tg*2;
                    const float pv = pos[(size_t)row * 2 + (c0 >> 4)];
                    float s0, cth0, s1, cth1;
                    __sincosf(pv * fr0[n], &s0, &cth0);
                    __sincosf(pv * fr1[n], &s1, &cth1);
                    const float x1a = acc[m][n][rr*2]     * rinv;
                    const float x1b = acc[m][n][rr*2+1]   * rinv;
                    const float x2a = acc[m][n+4][rr*2]   * rinv;
                    const float x2b = acc[m][n+4][rr*2+1] * rinv;
                    *(uint32_t*)(dst + ob + c0)      = pack2f(x1a*cth0 - x2a*s0, x1b*cth1 - x2b*s1);
                    *(uint32_t*)(dst + ob + c0 + 32) = pack2f(x2a*cth0 + x1a*s0, x2b*cth1 + x1b*s1);
                }
            }
    }
}

// ---------------- out GEMM (fp32 output) ----------------
__global__ __launch_bounds__(256, 2) void out_gemm_kernel(
    const __half* __restrict__ Ah,
    const __half* __restrict__ Bh, const __half* __restrict__ Bl,
    float* __restrict__ C)
{
    extern __shared__ char sm[];
    const uint32_t smb = smem_u32(sm);
    const int tid = threadIdx.x, lane = tid & 31, wid = tid >> 5;
    const int m0 = blockIdx.y * 128, n0 = blockIdx.x * 128;
    const int wm = (wid & 3) * 32, wn = (wid >> 2) * 64;
    const int K = DM, N = DM;

    float acc[2][8][4];
#pragma unroll
    for (int m = 0; m < 2; m++)
#pragma unroll
        for (int n = 0; n < 8; n++)
#pragma unroll
            for (int r = 0; r < 4; r++) acc[m][n][r] = 0.f;

    GEMM_MAINLOOP(Ah, Bh, Bl, K, N)

    const int g = lane >> 2, tg = lane & 3;
#pragma unroll
    for (int m = 0; m < 2; m++)
#pragma unroll
        for (int rr = 0; rr < 2; rr++) {
            int row = m0 + wm + m * 16 + g + rr * 8;
#pragma unroll
            for (int n = 0; n < 8; n++) {
                int col = n0 + wn + n * 8 + tg * 2;
                *(float2*)(C + (size_t)row * N + col) =
                    make_float2(acc[m][n][rr*2], acc[m][n][rr*2+1]);
            }
        }
}

// ---------------- attention via mma.sync (fp16 QKV, fp32 accum), 3-stage ----------------
#define AT_STRIDE 144
#define AT_QH 0
#define AT_KV0 (128 * AT_STRIDE)              // 18432
#define AT_ARR (64 * AT_STRIDE)               // 9216 per array
#define AT_BUF (2 * AT_ARR)                   // 18432 (Kh, Vh)
#define NKT (SEQL / 64)                       // 32
#define ATTN_SMEM (AT_KV0 + 3 * AT_BUF)       // 73728

static __device__ __forceinline__ void attn_load_kv(uint32_t smb, size_t bh,
                                                    int tid, int t, int bufi)
{
    const int k0 = t * 64;
    const int r  = tid >> 1;
    const int hc = (tid & 1) * 32;
    uint32_t base = smb + AT_KV0 + bufi * AT_BUF + r * AT_STRIDE + hc * 2;
    const __half* s0 = g_kh + (bh + k0 + r) * DE + hc;
    const __half* s1 = g_vh + (bh + k0 + r) * DE + hc;
#pragma unroll
    for (int c = 0; c < 4; c++) {
        cpasync16(base + 0*AT_ARR + c*16, s0 + c*8);
        cpasync16(base + 1*AT_ARR + c*16, s1 + c*8);
    }
}

__global__ __launch_bounds__(128) void attn_mma_kernel()
{
    extern __shared__ char sm[];
    const uint32_t smb = smem_u32(sm);
    const int tid = threadIdx.x, lane = tid & 31, wid = tid >> 5;
    const int q0 = blockIdx.x * 128, head = blockIdx.y, b = blockIdx.z;
    const size_t bh = (size_t)(b * NH + head) * SEQL;

    {
        const __half* qh = g_qh + (bh + q0 + tid) * DE;
        uint32_t dh = smb + AT_QH + tid * AT_STRIDE;
#pragma unroll
        for (int c = 0; c < 8; c++)
            cpasync16(dh + c*16, qh + c*8);
    }
    attn_load_kv(smb, bh, tid, 0, 0);
    CP_COMMIT();
    attn_load_kv(smb, bh, tid, 1, 1);
    CP_COMMIT();
    CP_WAIT1();                 // Q + kv0 resident
    __syncthreads();

    uint32_t qfr[2][4][4];
#pragma unroll
    for (int m = 0; m < 2; m++)
#pragma unroll
        for (int kt = 0; kt < 4; kt++) {
            const uint32_t qrow = wid*32 + m*16 + (lane & 15);
            const uint32_t qcol = kt * 32 + ((lane & 16) ? 16 : 0);
            ldsm4(qfr[m][kt], smb + AT_QH + qrow * AT_STRIDE + qcol);
        }

    float O[2][8][4];
#pragma unroll
    for (int m = 0; m < 2; m++)
#pragma unroll
        for (int n = 0; n < 8; n++)
#pragma unroll
            for (int r = 0; r < 4; r++) O[m][n][r] = 0.f;
    float lsacc[2][4];
#pragma unroll
    for (int m = 0; m < 2; m++)
#pragma unroll
        for (int r = 0; r < 4; r++) lsacc[m][r] = 0.f;
    const uint32_t ones2[2] = {0x3C003C00u, 0x3C003C00u};

    for (int t = 0; t < NKT; t++) {
        CP_WAIT1();                 // kv(t) resident, kv(t+1) in flight
        __syncthreads();
        if (t + 2 < NKT)
            attn_load_kv(smb, bh, tid, t + 2, (t + 2) % 3);
        CP_COMMIT();

        uint32_t kb  = smb + AT_KV0 + (t % 3) * AT_BUF;
        uint32_t kh_b = kb, vh_b = kb + AT_ARR;

        float S[2][8][4];
#pragma unroll
        for (int m = 0; m < 2; m++)
#pragma unroll
            for (int n = 0; n < 8; n++)
#pragma unroll
                for (int r = 0; r < 4; r++) S[m][n][r] = 0.f;

        // ---- S = Q K^T (Q pre-scaled: S already in log2 domain) ----
#pragma unroll
        for (int kt = 0; kt < 4; kt++) {
            uint32_t kfh[4][4];
            const uint32_t krow = (lane & 7) + ((lane & 16) ? 8 : 0);
            const uint32_t kcol = kt * 32 + ((lane & 8) ? 16 : 0);
#pragma unroll
            for (int np = 0; np < 4; np++)
                ldsm4(kfh[np], kh_b + (np*16 + krow) * AT_STRIDE + kcol);
#pragma unroll
            for (int m = 0; m < 2; m++)
#pragma unroll
                for (int np = 0; np < 4; np++) {
                    mma_f16(S[m][2*np],   qfr[m][kt], kfh[np]);
                    mma_f16(S[m][2*np+1], qfr[m][kt], kfh[np] + 2);
                }
        }

        // ---- P = exp2(S) via f16x2 MUFU, directly packed A-fragments ----
        uint32_t pa[2][4][4];
#pragma unroll
        for (int m = 0; m < 2; m++)
#pragma unroll
            for (int n = 0; n < 8; n++) {
                const int kt = n >> 1, rb = (n & 1) * 2;
                pa[m][kt][rb]     = exp2_h2(S[m][n][0], S[m][n][1]);
                pa[m][kt][rb + 1] = exp2_h2(S[m][n][2], S[m][n][3]);
            }

        // ---- lsum via ones-MMA (row sums accumulate in lsacc) ----
#pragma unroll
        for (int m = 0; m < 2; m++)
#pragma unroll
            for (int kt = 0; kt < 4; kt++)
                mma_f16(lsacc[m], pa[m][kt], ones2);

        // ---- O += P V ----
#pragma unroll
        for (int kt = 0; kt < 4; kt++) {
            uint32_t vfh[4][4];
            const uint32_t vrow = kt*16 + (lane & 7) + ((lane & 8) ? 8 : 0);
            const uint32_t vcol = ((lane & 16) ? 16 : 0);
#pragma unroll
            for (int np = 0; np < 4; np++)
                ldsm4t(vfh[np], vh_b + vrow * AT_STRIDE + np*32 + vcol);
#pragma unroll
            for (int m = 0; m < 2; m++)
#pragma unroll
                for (int np = 0; np < 4; np++) {
                    mma_f16(O[m][2*np],   pa[m][kt], vfh[np]);
                    mma_f16(O[m][2*np+1], pa[m][kt], vfh[np] + 2);
                }
        }
    }

    // ---- epilogue: rows g (lsacc[.][0]) and g+8 (lsacc[.][2]) ----
    const int g = lane >> 2, tg = lane & 3;
#pragma unroll
    for (int m = 0; m < 2; m++) {
#pragma unroll
        for (int rr = 0; rr < 2; rr++) {
            const int row = q0 + wid*32 + m*16 + g + rr*8;
            const float inv = 1.0f / lsacc[m][rr*2];
            const size_t rb = ((size_t)b * SEQL + row) * DM + head * DE;
#pragma unroll
            for (int n = 0; n < 8; n++) {
                const int col = n*8 + tg*2;
                *(uint32_t*)(g_oh + rb + col) =
                    pack2f(O[m][n][rr*2] * inv, O[m][n][rr*2+1] * inv);
            }
        }
    }
}

// ---------------- launch ----------------
extern "C" void kernel_launch(void* const* d_in, const int* in_sizes, int n_in,
                              void* d_out, int out_size)
{
    const float* x        = (const float*)d_in[0];
    const float* pos      = (const float*)d_in[1];
    const float* cond     = (const float*)d_in[2];
    const float* w_cond   = (const float*)d_in[3];
    const float* w_qkv    = (const float*)d_in[4];
    const float* qk_scale = (const float*)d_in[5];
    const float* w_out    = (const float*)d_in[6];
    float* out = (float*)d_out;

    __half *p_xnh, *p_oh, *p_wqh, *p_wql, *p_woh, *p_wol;
    cudaGetSymbolAddress((void**)&p_xnh, g_xnh);
    cudaGetSymbolAddress((void**)&p_oh,  g_oh);
    cudaGetSymbolAddress((void**)&p_wqh, g_wqh);
    cudaGetSymbolAddress((void**)&p_wql, g_wql);
    cudaGetSymbolAddress((void**)&p_woh, g_woh);
    cudaGetSymbolAddress((void**)&p_wol, g_wol);

    static int s_attr = 0;
    if (!s_attr) {
        cudaFuncSetAttribute(attn_mma_kernel,
                             cudaFuncAttributeMaxDynamicSharedMemorySize, ATTN_SMEM);
        cudaFuncSetAttribute(qkv_gemm_kernel,
                             cudaFuncAttributeMaxDynamicSharedMemorySize, GEMM_SMEM);
        cudaFuncSetAttribute(out_gemm_kernel,
                             cudaFuncAttributeMaxDynamicSharedMemorySize, GEMM_SMEM);
        s_attr = 1;
    }

    cond_partial_kernel<<<dim3(DM/256, NB, 8), 256>>>(cond, w_cond);         // 0
    cond_reduce_kernel<<<NB*DM/256, 256>>>();                                // 1
    fused_pre_kernel<<<FP_RMS + FP_WQ + FP_WO, 256>>>(x, w_qkv, w_out);      // 2
    qkv_gemm_kernel<<<dim3(3*DM/128, ROWS/128), 256, GEMM_SMEM>>>(           // 3 (profiled)
        p_xnh, p_wqh, p_wql, pos, qk_scale);
    attn_mma_kernel<<<dim3(SEQL/128, NH, NB), 128, ATTN_SMEM>>>();           // 4
    out_gemm_kernel<<<dim3(DM/128, ROWS/128), 256, GEMM_SMEM>>>(             // 5
        p_oh, p_woh, p_wol, out);
}

// round 12
// speedup vs baseline: 1.3088x; 1.0275x over previous
#include <cuda_runtime.h>
#include <cuda_fp16.h>
#include <math.h>
#include <stdint.h>

// Problem shape: n=2, l=2048, d_model=1024, h=16, e=64
#define NB 2
#define SEQL 2048
#define DM 1024
#define NH 16
#define DE 64
#define ROWS (NB * SEQL)          // 4096

// ---------------- scratch ----------------
__device__ float  g_cwp[8 * NB * DM];         // cond partials
__device__ float  g_cw[NB * DM];
__device__ __half g_xnh[ROWS * DM];
__device__ __half g_qh[NB*NH*SEQL*DE];
__device__ __half g_kh[NB*NH*SEQL*DE];
__device__ __half g_vh[NB*NH*SEQL*DE];
__device__ __half g_oh[ROWS * DM];
__device__ __half g_wqh[DM * 3 * DM], g_wql[DM * 3 * DM];
__device__ __half g_woh[DM * DM],     g_wol[DM * DM];

// ---------------- helpers ----------------
static __device__ __forceinline__ uint32_t smem_u32(const void* p) {
    uint32_t a;
    asm("{ .reg .u64 t; cvta.to.shared.u64 t, %1; cvt.u32.u64 %0, t; }" : "=r"(a) : "l"(p));
    return a;
}
static __device__ __forceinline__ void cpasync16(uint32_t dst, const void* src) {
    asm volatile("cp.async.cg.shared.global [%0], [%1], 16;" :: "r"(dst), "l"(src));
}
#define CP_COMMIT() asm volatile("cp.async.commit_group;" ::: "memory")
#define CP_WAIT1()  asm volatile("cp.async.wait_group 1;"  ::: "memory")
static __device__ __forceinline__ void ldsm4(uint32_t* r, uint32_t a) {
    asm volatile("ldmatrix.sync.aligned.m8n8.x4.shared.b16 {%0,%1,%2,%3}, [%4];"
        : "=r"(r[0]), "=r"(r[1]), "=r"(r[2]), "=r"(r[3]) : "r"(a));
}
static __device__ __forceinline__ void ldsm4t(uint32_t* r, uint32_t a) {
    asm volatile("ldmatrix.sync.aligned.m8n8.x4.trans.shared.b16 {%0,%1,%2,%3}, [%4];"
        : "=r"(r[0]), "=r"(r[1]), "=r"(r[2]), "=r"(r[3]) : "r"(a));
}
static __device__ __forceinline__ void mma_f16(float* c, const uint32_t* a, const uint32_t* b) {
    asm volatile("mma.sync.aligned.m16n8k16.row.col.f32.f16.f16.f32 "
        "{%0,%1,%2,%3}, {%4,%5,%6,%7}, {%8,%9}, {%0,%1,%2,%3};"
        : "+f"(c[0]), "+f"(c[1]), "+f"(c[2]), "+f"(c[3])
        : "r"(a[0]), "r"(a[1]), "r"(a[2]), "r"(a[3]), "r"(b[0]), "r"(b[1]));
}
static __device__ __forceinline__ float fast_exp2(float x) {
    float y; asm("ex2.approx.f32 %0, %1;" : "=f"(y) : "f"(x)); return y;
}
static __device__ __forceinline__ uint32_t pack2f(float a, float b) {
    __half2 h = __floats2half2_rn(a, b);
    return *(uint32_t*)&h;
}

// ---------------- cond GEMM: K-split partials + reduce ----------------
__global__ void cond_partial_kernel(const float* __restrict__ cond,
                                    const float* __restrict__ w_cond)
{
    __shared__ float cs[128];
    const int n  = blockIdx.y;
    const int ks = blockIdx.z;
    if (threadIdx.x < 128)
        cs[threadIdx.x] = cond[n * DM + ks * 128 + threadIdx.x];
    __syncthreads();
    const int j = blockIdx.x * blockDim.x + threadIdx.x;
    float acc = 0.f;
#pragma unroll 8
    for (int k = 0; k < 128; k++)
        acc = fmaf(cs[k], w_cond[(size_t)(ks * 128 + k) * DM + j], acc);
    g_cwp[(ks * NB + n) * DM + j] = acc;
}
__global__ void cond_reduce_kernel()
{
    const int i = blockIdx.x * blockDim.x + threadIdx.x;
    const int n = i / DM, j = i % DM;
    float s = 1.0f;
#pragma unroll
    for (int ks = 0; ks < 8; ks++)
        s += g_cwp[(ks * NB + n) * DM + j];
    g_cw[i] = s;
}

// ---------------- fused: rmsnorm(x) + split(w_qkv) + split(w_out) ----------------
#define FP_RMS   ROWS
#define FP_WQ    (DM * 3 * DM / 256)     // 12288
#define FP_WO    (DM * DM / 256)         // 4096
__global__ void fused_pre_kernel(const float* __restrict__ x,
                                 const float* __restrict__ w_qkv,
                                 const float* __restrict__ w_out)
{
    const int b = blockIdx.x;
    const int t = threadIdx.x;
    if (b < FP_RMS) {
        const int row = b;
        const int n = row / SEQL;
        float4 v = *(const float4*)(x + (size_t)row * DM + t * 4);
        float ss = v.x * v.x + v.y * v.y + v.z * v.z + v.w * v.w;
#pragma unroll
        for (int o = 16; o > 0; o >>= 1)
            ss += __shfl_xor_sync(0xffffffffu, ss, o);
        __shared__ float ws[8];
        if ((t & 31) == 0) ws[t >> 5] = ss;
        __syncthreads();
        float tot = ws[0]+ws[1]+ws[2]+ws[3]+ws[4]+ws[5]+ws[6]+ws[7];
        float rinv = rsqrtf(tot * (1.0f / DM) + 1e-6f);
        float4 cwv = *(const float4*)(g_cw + n * DM + t * 4);
        size_t base = (size_t)row * DM + t * 4;
        *(uint32_t*)(g_xnh + base)     = pack2f(v.x * cwv.x * rinv, v.y * cwv.y * rinv);
        *(uint32_t*)(g_xnh + base + 2) = pack2f(v.z * cwv.z * rinv, v.w * cwv.w * rinv);
    } else if (b < FP_RMS + FP_WQ) {
        int i = (b - FP_RMS) * 256 + t;
        float v = w_qkv[i];
        __half hh = __float2half_rn(v);
        g_wqh[i] = hh;
        g_wql[i] = __float2half_rn(v - __half2float(hh));
    } else {
        int i = (b - FP_RMS - FP_WQ) * 256 + t;
        float v = w_out[i];
        __half hh = __float2half_rn(v);
        g_woh[i] = hh;
        g_wol[i] = __float2half_rn(v - __half2float(hh));
    }
}

// ---------------- GEMM core: BM=128, BN=128, BK=32, 3-stage ----------------
#define GM_ASTRIDE 80
#define GM_BSTRIDE 272
#define GM_A_SZ (128 * GM_ASTRIDE)            // 10240
#define GM_B_SZ (32 * GM_BSTRIDE)             // 8704
#define GM_BUF (GM_A_SZ + 2*GM_B_SZ)          // 27648
#define GEMM_SMEM (3 * GM_BUF)                // 82944

static __device__ __forceinline__ void gemm_load(uint32_t smb, int bufi,
    const __half* Ah, const __half* Bh, const __half* Bl,
    int m0, int n0, int k0, int K, int N, int tid)
{
    uint32_t base = smb + bufi * GM_BUF;
    const int ar = tid >> 1, ac = (tid & 1) * 16;
    const __half* pah = Ah + (size_t)(m0 + ar) * K + k0 + ac;
    cpasync16(base + ar*GM_ASTRIDE + ac*2,      pah);
    cpasync16(base + ar*GM_ASTRIDE + ac*2 + 16, pah + 8);
    const int br = tid >> 3, bc = (tid & 7) * 16;
    const __half* pbh = Bh + (size_t)(k0 + br) * N + n0 + bc;
    const __half* pbl = Bl + (size_t)(k0 + br) * N + n0 + bc;
    uint32_t bb = base + GM_A_SZ;
    cpasync16(bb + br*GM_BSTRIDE + bc*2,      pbh);
    cpasync16(bb + br*GM_BSTRIDE + bc*2 + 16, pbh + 8);
    cpasync16(bb + GM_B_SZ + br*GM_BSTRIDE + bc*2,      pbl);
    cpasync16(bb + GM_B_SZ + br*GM_BSTRIDE + bc*2 + 16, pbl + 8);
}

#define GEMM_MAINLOOP(Ah, Bh, Bl, K, N)                                         \
    const int nk = (K) / 32;                                                    \
    gemm_load(smb, 0, Ah, Bh, Bl, m0, n0, 0, K, N, tid);                        \
    CP_COMMIT();                                                                \
    gemm_load(smb, 1, Ah, Bh, Bl, m0, n0, 32, K, N, tid);                       \
    CP_COMMIT();                                                                \
    for (int s = 0; s < nk; s++) {                                              \
        CP_WAIT1();                                                             \
        __syncthreads();                                                        \
        if (s + 2 < nk)                                                         \
            gemm_load(smb, (s + 2) % 3, Ah, Bh, Bl, m0, n0, (s + 2) * 32, K, N, tid); \
        CP_COMMIT();                                                            \
        uint32_t base = smb + (s % 3) * GM_BUF;                                 \
        uint32_t a_h = base;                                                    \
        uint32_t b_h = base + GM_A_SZ, b_l = b_h + GM_B_SZ;                     \
        _Pragma("unroll")                                                       \
        for (int kt = 0; kt < 2; kt++) {                                        \
            uint32_t bfh[4][4], bfl[4][4];                                      \
            const uint32_t brow = kt * 16 + (lane & 7) + ((lane & 8) ? 8 : 0);  \
            const uint32_t bcol = wn * 2 + ((lane & 16) ? 16 : 0);              \
            _Pragma("unroll")                                                   \
            for (int np = 0; np < 4; np++) {                                    \
                ldsm4t(bfh[np], b_h + brow * GM_BSTRIDE + bcol + np * 32);      \
                ldsm4t(bfl[np], b_l + brow * GM_BSTRIDE + bcol + np * 32);      \
            }                                                                   \
            _Pragma("unroll")                                                   \
            for (int m = 0; m < 2; m++) {                                       \
                uint32_t afh[4];                                                \
                const uint32_t arow = wm + m * 16 + (lane & 15);                \
                const uint32_t acol = kt * 32 + ((lane & 16) ? 16 : 0);         \
                ldsm4(afh, a_h + arow * GM_ASTRIDE + acol);                     \
                _Pragma("unroll")                                               \
                for (int np = 0; np < 4; np++) {                                \
                    mma_f16(acc[m][2*np],   afh, bfh[np]);                      \
                    mma_f16(acc[m][2*np+1], afh, bfh[np] + 2);                  \
                    mma_f16(acc[m][2*np],   afh, bfl[np]);                      \
                    mma_f16(acc[m][2*np+1], afh, bfl[np] + 2);                  \
                }                                                               \
            }                                                                   \
        }                                                                       \
    }

// ---------------- QKV GEMM with fused qk-rmsnorm + rope epilogue ----------------
// Q additionally pre-scaled by log2(e)/8 so attention scores come out of the
// S-MMA already in log2 domain.
__global__ __launch_bounds__(256, 2) void qkv_gemm_kernel(
    const __half* __restrict__ Ah,
    const __half* __restrict__ Bh, const __half* __restrict__ Bl,
    const float* __restrict__ pos, const float* __restrict__ qk_scale)
{
    extern __shared__ char sm[];
    const uint32_t smb = smem_u32(sm);
    const int tid = threadIdx.x, lane = tid & 31, wid = tid >> 5;
    const int m0 = blockIdx.y * 128, n0 = blockIdx.x * 128;
    const int wm = (wid & 3) * 32, wn = (wid >> 2) * 64;
    const int K = DM, N = 3 * DM;

    float acc[2][8][4];
#pragma unroll
    for (int m = 0; m < 2; m++)
#pragma unroll
        for (int n = 0; n < 8; n++)
#pragma unroll
            for (int r = 0; r < 4; r++) acc[m][n][r] = 0.f;

    GEMM_MAINLOOP(Ah, Bh, Bl, K, N)

    const int g = lane >> 2, tg = lane & 3;
    const int region = n0 >> 10;                    // 0 Q, 1 K, 2 V
    const int head = ((n0 + wn) & 1023) >> 6;
    const size_t hb = (size_t)head * SEQL * DE;

    if (region == 2) {
#pragma unroll
        for (int m = 0; m < 2; m++)
#pragma unroll
            for (int rr = 0; rr < 2; rr++) {
                const int row = m0 + wm + m*16 + g + rr*8;
                const int nb = row >> 11, l = row & (SEQL - 1);
                const size_t ob = (size_t)nb * NH * SEQL * DE + hb + (size_t)l * DE;
#pragma unroll
                for (int n = 0; n < 8; n++) {
                    const int c = n*8 + tg*2;
                    *(uint32_t*)(g_vh + ob + c) = pack2f(acc[m][n][rr*2], acc[m][n][rr*2+1]);
                }
            }
    } else {
        __half* dst = region ? g_kh : g_qh;
        float sc = expf(0.5f * fminf(qk_scale[head], 4.6051701860f) - 1.0397207708f);
        if (region == 0) sc *= 0.18033688011112042f;   // log2(e)/8 folded into Q
        float fr0[4], fr1[4];
#pragma unroll
        for (int n = 0; n < 4; n++) {
            const int c0 = n*8 + tg*2;
            fr0[n] = expf(1.14472988584940017f + (float)((c0 & 15) * 16 + head) * (2.30258509299404568f / 256.0f));
            fr1[n] = expf(1.14472988584940017f + (float)(((c0+1) & 15) * 16 + head) * (2.30258509299404568f / 256.0f));
        }
#pragma unroll
        for (int m = 0; m < 2; m++)
#pragma unroll
            for (int rr = 0; rr < 2; rr++) {
                float ss = 0.f;
#pragma unroll
                for (int n = 0; n < 8; n++) {
                    float a0 = acc[m][n][rr*2], a1 = acc[m][n][rr*2+1];
                    ss += a0*a0 + a1*a1;
                }
                ss += __shfl_xor_sync(0xffffffffu, ss, 1);
                ss += __shfl_xor_sync(0xffffffffu, ss, 2);
                const float rinv = sc * rsqrtf(ss * (1.0f / DE) + 1e-6f);

                const int row = m0 + wm + m*16 + g + rr*8;
                const int nb = row >> 11, l = row & (SEQL - 1);
                const size_t ob = (size_t)nb * NH * SEQL * DE + hb + (size_t)l * DE;
#pragma unroll
                for (int n = 0; n < 4; n++) {
                    const int c0 = n*8 + tg*2;
                    const float pv = pos[(size_t)row * 2 + (c0 >> 4)];
                    float s0, cth0, s1, cth1;
                    __sincosf(pv * fr0[n], &s0, &cth0);
                    __sincosf(pv * fr1[n], &s1, &cth1);
                    const float x1a = acc[m][n][rr*2]     * rinv;
                    const float x1b = acc[m][n][rr*2+1]   * rinv;
                    const float x2a = acc[m][n+4][rr*2]   * rinv;
                    const float x2b = acc[m][n+4][rr*2+1] * rinv;
                    *(uint32_t*)(dst + ob + c0)      = pack2f(x1a*cth0 - x2a*s0, x1b*cth1 - x2b*s1);
                    *(uint32_t*)(dst + ob + c0 + 32) = pack2f(x2a*cth0 + x1a*s0, x2b*cth1 + x1b*s1);
                }
            }
    }
}

// ---------------- out GEMM (fp32 output) ----------------
__global__ __launch_bounds__(256, 2) void out_gemm_kernel(
    const __half* __restrict__ Ah,
    const __half* __restrict__ Bh, const __half* __restrict__ Bl,
    float* __restrict__ C)
{
    extern __shared__ char sm[];
    const uint32_t smb = smem_u32(sm);
    const int tid = threadIdx.x, lane = tid & 31, wid = tid >> 5;
    const int m0 = blockIdx.y * 128, n0 = blockIdx.x * 128;
    const int wm = (wid & 3) * 32, wn = (wid >> 2) * 64;
    const int K = DM, N = DM;

    float acc[2][8][4];
#pragma unroll
    for (int m = 0; m < 2; m++)
#pragma unroll
        for (int n = 0; n < 8; n++)
#pragma unroll
            for (int r = 0; r < 4; r++) acc[m][n][r] = 0.f;

    GEMM_MAINLOOP(Ah, Bh, Bl, K, N)

    const int g = lane >> 2, tg = lane & 3;
#pragma unroll
    for (int m = 0; m < 2; m++)
#pragma unroll
        for (int rr = 0; rr < 2; rr++) {
            int row = m0 + wm + m * 16 + g + rr * 8;
#pragma unroll
            for (int n = 0; n < 8; n++) {
                int col = n0 + wn + n * 8 + tg * 2;
                *(float2*)(C + (size_t)row * N + col) =
                    make_float2(acc[m][n][rr*2], acc[m][n][rr*2+1]);
            }
        }
}

// ---------------- attention: 256 threads, 8 warps (16 q-rows each), 3-stage ----------------
#define AT_STRIDE 144
#define AT_QH 0
#define AT_KV0 (128 * AT_STRIDE)              // 18432
#define AT_ARR (64 * AT_STRIDE)               // 9216 per array
#define AT_BUF (2 * AT_ARR)                   // 18432 (Kh, Vh)
#define NKT (SEQL / 64)                       // 32
#define ATTN_SMEM (AT_KV0 + 3 * AT_BUF)       // 73728

static __device__ __forceinline__ void attn_load_kv(uint32_t smb, size_t bh,
                                                    int tid, int t, int bufi)
{
    const int k0 = t * 64;
    const int r  = tid >> 2;                  // 0..63
    const int hc = (tid & 3) * 16;            // 0,16,32,48 halves
    uint32_t base = smb + AT_KV0 + bufi * AT_BUF + r * AT_STRIDE + hc * 2;
    const __half* s0 = g_kh + (bh + k0 + r) * DE + hc;
    const __half* s1 = g_vh + (bh + k0 + r) * DE + hc;
#pragma unroll
    for (int c = 0; c < 2; c++) {
        cpasync16(base + 0*AT_ARR + c*16, s0 + c*8);
        cpasync16(base + 1*AT_ARR + c*16, s1 + c*8);
    }
}

__global__ __launch_bounds__(256, 2) void attn_mma_kernel()
{
    extern __shared__ char sm[];
    const uint32_t smb = smem_u32(sm);
    const int tid = threadIdx.x, lane = tid & 31, wid = tid >> 5;
    const int q0 = blockIdx.x * 128, head = blockIdx.y, b = blockIdx.z;
    const size_t bh = (size_t)(b * NH + head) * SEQL;

    // Q -> smem: 128 rows x 64 halves; thread: row tid>>1, half (tid&1)*32
    {
        const int r = tid >> 1, hc = (tid & 1) * 32;
        const __half* qh = g_qh + (bh + q0 + r) * DE + hc;
        uint32_t dh = smb + AT_QH + r * AT_STRIDE + hc * 2;
#pragma unroll
        for (int c = 0; c < 4; c++)
            cpasync16(dh + c*16, qh + c*8);
    }
    attn_load_kv(smb, bh, tid, 0, 0);
    CP_COMMIT();
    attn_load_kv(smb, bh, tid, 1, 1);
    CP_COMMIT();
    CP_WAIT1();                 // Q + kv0 resident
    __syncthreads();

    // hoist Q fragments: warp owns 16 q-rows [wid*16, wid*16+16)
    uint32_t qfr[4][4];
#pragma unroll
    for (int kt = 0; kt < 4; kt++) {
        const uint32_t qrow = wid*16 + (lane & 15);
        const uint32_t qcol = kt * 32 + ((lane & 16) ? 16 : 0);
        ldsm4(qfr[kt], smb + AT_QH + qrow * AT_STRIDE + qcol);
    }

    float O[8][4];
#pragma unroll
    for (int n = 0; n < 8; n++)
#pragma unroll
        for (int r = 0; r < 4; r++) O[n][r] = 0.f;
    float lsacc[4] = {0.f, 0.f, 0.f, 0.f};
    const uint32_t ones2[2] = {0x3C003C00u, 0x3C003C00u};

    for (int t = 0; t < NKT; t++) {
        CP_WAIT1();                 // kv(t) resident, kv(t+1) in flight
        __syncthreads();
        if (t + 2 < NKT)
            attn_load_kv(smb, bh, tid, t + 2, (t + 2) % 3);
        CP_COMMIT();

        uint32_t kb  = smb + AT_KV0 + (t % 3) * AT_BUF;
        uint32_t kh_b = kb, vh_b = kb + AT_ARR;

        float S[8][4];
#pragma unroll
        for (int n = 0; n < 8; n++)
#pragma unroll
            for (int r = 0; r < 4; r++) S[n][r] = 0.f;

        // ---- S = Q K^T (Q pre-scaled: S already in log2 domain) ----
#pragma unroll
        for (int kt = 0; kt < 4; kt++) {
            uint32_t kfh[4][4];
            const uint32_t krow = (lane & 7) + ((lane & 16) ? 8 : 0);
            const uint32_t kcol = kt * 32 + ((lane & 8) ? 16 : 0);
#pragma unroll
            for (int np = 0; np < 4; np++)
                ldsm4(kfh[np], kh_b + (np*16 + krow) * AT_STRIDE + kcol);
#pragma unroll
            for (int np = 0; np < 4; np++) {
                mma_f16(S[2*np],   qfr[kt], kfh[np]);
                mma_f16(S[2*np+1], qfr[kt], kfh[np] + 2);
            }
        }

        // ---- P = exp2(S) fp32 MUFU -> fp16 A-fragments ----
        uint32_t pa[4][4];
#pragma unroll
        for (int n = 0; n < 8; n++) {
            float p0 = fast_exp2(S[n][0]);
            float p1 = fast_exp2(S[n][1]);
            float p2 = fast_exp2(S[n][2]);
            float p3 = fast_exp2(S[n][3]);
            const int kt = n >> 1, rb = (n & 1) * 2;
            pa[kt][rb]     = pack2f(p0, p1);
            pa[kt][rb + 1] = pack2f(p2, p3);
        }

        // ---- lsum via ones-MMA ----
#pragma unroll
        for (int kt = 0; kt < 4; kt++)
            mma_f16(lsacc, pa[kt], ones2);

        // ---- O += P V ----
#pragma unroll
        for (int kt = 0; kt < 4; kt++) {
            uint32_t vfh[4][4];
            const uint32_t vrow = kt*16 + (lane & 7) + ((lane & 8) ? 8 : 0);
            const uint32_t vcol = ((lane & 16) ? 16 : 0);
#pragma unroll
            for (int np = 0; np < 4; np++)
                ldsm4t(vfh[np], vh_b + vrow * AT_STRIDE + np*32 + vcol);
#pragma unroll
            for (int np = 0; np < 4; np++) {
                mma_f16(O[2*np],   pa[kt], vfh[np]);
                mma_f16(O[2*np+1], pa[kt], vfh[np] + 2);
            }
        }
    }

    // ---- epilogue: rows g (lsacc[0]) and g+8 (lsacc[2]) ----
    const int g = lane >> 2, tg = lane & 3;
#pragma unroll
    for (int rr = 0; rr < 2; rr++) {
        const int row = q0 + wid*16 + g + rr*8;
        const float inv = 1.0f / lsacc[rr*2];
        const size_t rb = ((size_t)b * SEQL + row) * DM + head * DE;
#pragma unroll
        for (int n = 0; n < 8; n++) {
            const int col = n*8 + tg*2;
            *(uint32_t*)(g_oh + rb + col) =
                pack2f(O[n][rr*2] * inv, O[n][rr*2+1] * inv);
        }
    }
}

// ---------------- launch ----------------
extern "C" void kernel_launch(void* const* d_in, const int* in_sizes, int n_in,
                              void* d_out, int out_size)
{
    const float* x        = (const float*)d_in[0];
    const float* pos      = (const float*)d_in[1];
    const float* cond     = (const float*)d_in[2];
    const float* w_cond   = (const float*)d_in[3];
    const float* w_qkv    = (const float*)d_in[4];
    const float* qk_scale = (const float*)d_in[5];
    const float* w_out    = (const float*)d_in[6];
    float* out = (float*)d_out;

    __half *p_xnh, *p_oh, *p_wqh, *p_wql, *p_woh, *p_wol;
    cudaGetSymbolAddress((void**)&p_xnh, g_xnh);
    cudaGetSymbolAddress((void**)&p_oh,  g_oh);
    cudaGetSymbolAddress((void**)&p_wqh, g_wqh);
    cudaGetSymbolAddress((void**)&p_wql, g_wql);
    cudaGetSymbolAddress((void**)&p_woh, g_woh);
    cudaGetSymbolAddress((void**)&p_wol, g_wol);

    static int s_attr = 0;
    if (!s_attr) {
        cudaFuncSetAttribute(attn_mma_kernel,
                             cudaFuncAttributeMaxDynamicSharedMemorySize, ATTN_SMEM);
        cudaFuncSetAttribute(qkv_gemm_kernel,
                             cudaFuncAttributeMaxDynamicSharedMemorySize, GEMM_SMEM);
        cudaFuncSetAttribute(out_gemm_kernel,
                             cudaFuncAttributeMaxDynamicSharedMemorySize, GEMM_SMEM);
        s_attr = 1;
    }

    cond_partial_kernel<<<dim3(DM/256, NB, 8), 256>>>(cond, w_cond);         // 0
    cond_reduce_kernel<<<NB*DM/256, 256>>>();                                // 1
    fused_pre_kernel<<<FP_RMS + FP_WQ + FP_WO, 256>>>(x, w_qkv, w_out);      // 2
    qkv_gemm_kernel<<<dim3(3*DM/128, ROWS/128), 256, GEMM_SMEM>>>(           // 3 (profiled)
        p_xnh, p_wqh, p_wql, pos, qk_scale);
    attn_mma_kernel<<<dim3(SEQL/128, NH, NB), 256, ATTN_SMEM>>>();           // 4
    out_gemm_kernel<<<dim3(DM/128, ROWS/128), 256, GEMM_SMEM>>>(             // 5
        p_oh, p_woh, p_wol, out);
}